// round 3
// baseline (speedup 1.0000x reference)
#include <cuda_runtime.h>

#define ALPHA 0.2f

// Aggregated edge features scratch: [128*75, 192] = 7.37 MB (static, allowed)
static __device__ float g_agg[9600 * 192];

__device__ __forceinline__ float lrelu(float v) { return v > 0.0f ? v : ALPHA * v; }

// packed f32x2 FMA: acc.lo += a.lo*b.lo; acc.hi += a.hi*b.hi
#define FFMA2(acc, a, b) \
    asm("fma.rn.f32x2 %0, %1, %2, %0;" : "+l"(acc) : "l"(a), "l"(b))

__device__ __forceinline__ float2 unpack2(unsigned long long v) {
    float2 r;
    asm("mov.b64 {%0, %1}, %2;" : "=f"(r.x), "=f"(r.y) : "l"(v));
    return r;
}

// ---------------- Edge kernel: persistent CTAs, one (b,i) at a time ----------------
// SMEM layout (floats). W2/W3 stored k-pair interleaved:
//   s[O_W2 + (k2*160 + c)*2 + p] = w2[(2*k2+p)*160 + c]
#define O_W1 0        // 7*96   = 672
#define O_W2 672      // 96*160 = 15360 (paired)
#define O_W3 16032    // 160*192= 30720 (paired)
#define O_B2 46752    // 160
#define O_B3 46912    // 192
#define O_UI 47104    // 96   (b1 + x_i @ W1[0:3])
#define O_XJ 47200    // 75*3 (pad to 228)
#define O_D  47428    // 75   (pad to 76)
#define O_H1 47504    // 25 rows * stride 100 = 2500
#define O_H2 50004    // 25 rows * stride 164 = 4100
#define O_AG 54104    // 192
#define SMEM1_FL 54296
#define SMEM1_BYTES (SMEM1_FL * 4)

__global__ void __launch_bounds__(256, 1)
edge_kernel(const float* __restrict__ x,
            const float* __restrict__ w1, const float* __restrict__ b1,
            const float* __restrict__ w2, const float* __restrict__ b2,
            const float* __restrict__ w3, const float* __restrict__ b3)
{
    extern __shared__ float s[];
    const int tid = threadIdx.x;

    // ---- One-time weight load (W2/W3 permuted to k-pair layout) ----
    {
        float4* d; const float4* g;
        d = (float4*)(s + O_W1); g = (const float4*)w1;
        for (int i = tid; i < 672 / 4; i += 256) d[i] = g[i];
        for (int idx = tid; idx < 96 * 160; idx += 256) {
            int k = idx / 160, c = idx - k * 160;
            s[O_W2 + ((k >> 1) * 160 + c) * 2 + (k & 1)] = w2[idx];
        }
        for (int idx = tid; idx < 160 * 192; idx += 256) {
            int k = idx / 192, c = idx - k * 192;
            s[O_W3 + ((k >> 1) * 192 + c) * 2 + (k & 1)] = w3[idx];
        }
        d = (float4*)(s + O_B2); g = (const float4*)b2;
        for (int i = tid; i < 160 / 4; i += 256) d[i] = g[i];
        d = (float4*)(s + O_B3); g = (const float4*)b3;
        for (int i = tid; i < 192 / 4; i += 256) d[i] = g[i];
    }

    // TRANSPOSED lane mapping: rg = tid % 5 (h-row dedup within warp),
    // cg = tid / 5 (only ~7 distinct weight addrs per warp -> SMEM multicast).
    // L2: 200 threads = 40 colgroups x 5 rowgroups
    const int rg2 = tid % 5, cg2 = tid / 5;
    const int ca2 = 2 * cg2, cb2 = 80 + 2 * cg2;
    // L3: 240 threads = 48 colgroups x 5 rowgroups
    const int rg3 = tid % 5, cg3 = tid / 5;
    const int ca3 = 2 * cg3, cb3 = 96 + 2 * cg3;

    for (int bi = blockIdx.x; bi < 9600; bi += gridDim.x) {
        const int b = bi / 75, i = bi % 75;
        const float* xb = x + b * 75 * 3;
        const float xi0 = xb[i * 3 + 0], xi1 = xb[i * 3 + 1], xi2 = xb[i * 3 + 2];

        if (tid < 75) {
            float a0 = xb[tid * 3 + 0], a1 = xb[tid * 3 + 1], a2 = xb[tid * 3 + 2];
            s[O_XJ + 3 * tid + 0] = a0;
            s[O_XJ + 3 * tid + 1] = a1;
            s[O_XJ + 3 * tid + 2] = a2;
            float d0 = (a0 - xi0) + 1e-12f;
            float d1 = (a1 - xi1) + 1e-12f;
            float d2 = (a2 - xi2) + 1e-12f;
            s[O_D + tid] = sqrtf(d0 * d0 + d1 * d1 + d2 * d2);
        }
        if (tid < 192) s[O_AG + tid] = 0.0f;
        __syncthreads();   // also covers weight load on first iteration

        // U_i[c] = b1[c] + x_i @ W1[0:3, c]
        if (tid < 96)
            s[O_UI + tid] = b1[tid] + xi0 * s[O_W1 + tid]
                                    + xi1 * s[O_W1 + 96 + tid]
                                    + xi2 * s[O_W1 + 192 + tid];
        __syncthreads();

        float ag0 = 0.f, ag1 = 0.f, ag2 = 0.f, ag3 = 0.f;

        for (int t = 0; t < 3; t++) {
            const int j0 = t * 25;

            // ---- Layer 1: h1[25][96] ----
            for (int idx = tid; idx < 25 * 96; idx += 256) {
                int r = idx / 96, c = idx - r * 96;
                int j = j0 + r;
                float v = s[O_UI + c]
                        + s[O_XJ + 3 * j + 0] * s[O_W1 + 288 + c]
                        + s[O_XJ + 3 * j + 1] * s[O_W1 + 384 + c]
                        + s[O_XJ + 3 * j + 2] * s[O_W1 + 480 + c]
                        + s[O_D + j]          * s[O_W1 + 576 + c];
                s[O_H1 + r * 100 + c] = lrelu(v);
            }
            __syncthreads();

            // ---- Layer 2: h2[25][160] = lrelu(h1 @ W2 + b2), FFMA2 ----
            if (tid < 200) {
                const int r0 = rg2 * 5;
                unsigned long long acc[5][4];
                #pragma unroll
                for (int m = 0; m < 5; m++)
                    { acc[m][0]=0ULL; acc[m][1]=0ULL; acc[m][2]=0ULL; acc[m][3]=0ULL; }
                const float* h1b = s + O_H1 + r0 * 100;
                const float* w2p = s + O_W2;
                #pragma unroll 2
                for (int k2 = 0; k2 < 48; k2++) {
                    ulonglong2 wa = *(const ulonglong2*)(w2p + (k2 * 160 + ca2) * 2);
                    ulonglong2 wb = *(const ulonglong2*)(w2p + (k2 * 160 + cb2) * 2);
                    #pragma unroll
                    for (int m = 0; m < 5; m++) {
                        unsigned long long hp =
                            *(const unsigned long long*)(h1b + m * 100 + 2 * k2);
                        FFMA2(acc[m][0], hp, wa.x);
                        FFMA2(acc[m][1], hp, wa.y);
                        FFMA2(acc[m][2], hp, wb.x);
                        FFMA2(acc[m][3], hp, wb.y);
                    }
                }
                float ba0 = s[O_B2 + ca2], ba1 = s[O_B2 + ca2 + 1];
                float bb0 = s[O_B2 + cb2], bb1 = s[O_B2 + cb2 + 1];
                #pragma unroll
                for (int m = 0; m < 5; m++) {
                    float2 p0 = unpack2(acc[m][0]);
                    float2 p1 = unpack2(acc[m][1]);
                    float2 p2 = unpack2(acc[m][2]);
                    float2 p3 = unpack2(acc[m][3]);
                    float* hr = s + O_H2 + (r0 + m) * 164;
                    hr[ca2]     = lrelu(p0.x + p0.y + ba0);
                    hr[ca2 + 1] = lrelu(p1.x + p1.y + ba1);
                    hr[cb2]     = lrelu(p2.x + p2.y + bb0);
                    hr[cb2 + 1] = lrelu(p3.x + p3.y + bb1);
                }
            }
            __syncthreads();

            // ---- Layer 3 + aggregation, FFMA2 ----
            if (tid < 240) {
                const int r0 = rg3 * 5;
                unsigned long long acc[5][4];
                #pragma unroll
                for (int m = 0; m < 5; m++)
                    { acc[m][0]=0ULL; acc[m][1]=0ULL; acc[m][2]=0ULL; acc[m][3]=0ULL; }
                const float* h2b = s + O_H2 + r0 * 164;
                const float* w3p = s + O_W3;
                #pragma unroll 2
                for (int k2 = 0; k2 < 80; k2++) {
                    ulonglong2 wa = *(const ulonglong2*)(w3p + (k2 * 192 + ca3) * 2);
                    ulonglong2 wb = *(const ulonglong2*)(w3p + (k2 * 192 + cb3) * 2);
                    #pragma unroll
                    for (int m = 0; m < 5; m++) {
                        unsigned long long hp =
                            *(const unsigned long long*)(h2b + m * 164 + 2 * k2);
                        FFMA2(acc[m][0], hp, wa.x);
                        FFMA2(acc[m][1], hp, wa.y);
                        FFMA2(acc[m][2], hp, wb.x);
                        FFMA2(acc[m][3], hp, wb.y);
                    }
                }
                float ba0 = s[O_B3 + ca3], ba1 = s[O_B3 + ca3 + 1];
                float bb0 = s[O_B3 + cb3], bb1 = s[O_B3 + cb3 + 1];
                #pragma unroll
                for (int m = 0; m < 5; m++) {
                    float2 p0 = unpack2(acc[m][0]);
                    float2 p1 = unpack2(acc[m][1]);
                    float2 p2 = unpack2(acc[m][2]);
                    float2 p3 = unpack2(acc[m][3]);
                    ag0 += lrelu(p0.x + p0.y + ba0);
                    ag1 += lrelu(p1.x + p1.y + ba1);
                    ag2 += lrelu(p2.x + p2.y + bb0);
                    ag3 += lrelu(p3.x + p3.y + bb1);
                }
            }
            __syncthreads();   // protect H1/H2 before next tile overwrites
        }

        if (tid < 240) {
            atomicAdd(&s[O_AG + ca3],     ag0);
            atomicAdd(&s[O_AG + ca3 + 1], ag1);
            atomicAdd(&s[O_AG + cb3],     ag2);
            atomicAdd(&s[O_AG + cb3 + 1], ag3);
        }
        __syncthreads();
        if (tid < 192) g_agg[bi * 192 + tid] = s[O_AG + tid];
        __syncthreads();   // O_AG/O_XJ reused next iteration
    }
}

// ---------------- Node kernel: one CTA per 32 rows (unchanged) ----------------
#define O2_Y 0         // 32 * 200 = 6400 (195 used)
#define O2_H 6400      // 32 * 260 = 8320
#define O2_W 14720     // up to 65*256 = 16640
#define SMEM2_FL 31360
#define SMEM2_BYTES (SMEM2_FL * 4)

__global__ void __launch_bounds__(256, 1)
node_kernel(const float* __restrict__ x,
            const float* __restrict__ w1, const float* __restrict__ b1,
            const float* __restrict__ w2, const float* __restrict__ b2,
            const float* __restrict__ w3, const float* __restrict__ b3,
            float* __restrict__ out)
{
    extern __shared__ float s[];
    const int tid = threadIdx.x;
    const int row0 = blockIdx.x * 32;

    for (int idx = tid; idx < 32 * 192; idx += 256) {
        int r = idx / 192, c = idx - r * 192;
        s[O2_Y + r * 200 + c] = g_agg[(row0 + r) * 192 + c];
    }
    for (int idx = tid; idx < 96; idx += 256) {
        int r = idx / 3, c = idx - r * 3;
        s[O2_Y + r * 200 + 192 + c] = x[(row0 + r) * 3 + c];
    }

    const int cg = tid % 64, rg = tid / 64;
    const int c0 = cg * 4, r0 = rg * 8;

    float acc[8][4];
    #pragma unroll
    for (int m = 0; m < 8; m++)
        { acc[m][0]=0.f; acc[m][1]=0.f; acc[m][2]=0.f; acc[m][3]=0.f; }
    for (int kc = 0; kc < 3; kc++) {
        __syncthreads();
        {
            float4* d = (float4*)(s + O2_W);
            const float4* g = (const float4*)(w1 + kc * 65 * 256);
            for (int i = tid; i < (65 * 256) / 4; i += 256) d[i] = g[i];
        }
        __syncthreads();
        const int kbase = kc * 65;
        for (int k = 0; k < 65; k++) {
            float4 w = *(const float4*)(s + O2_W + k * 256 + c0);
            #pragma unroll
            for (int m = 0; m < 8; m++) {
                float h = s[O2_Y + (r0 + m) * 200 + kbase + k];
                acc[m][0] += h * w.x; acc[m][1] += h * w.y;
                acc[m][2] += h * w.z; acc[m][3] += h * w.w;
            }
        }
    }
    __syncthreads();
    {
        float4 bb = *(const float4*)(b1 + c0);
        #pragma unroll
        for (int m = 0; m < 8; m++) {
            float4 o;
            o.x = lrelu(acc[m][0] + bb.x);
            o.y = lrelu(acc[m][1] + bb.y);
            o.z = lrelu(acc[m][2] + bb.z);
            o.w = lrelu(acc[m][3] + bb.w);
            *(float4*)(s + O2_H + (r0 + m) * 260 + c0) = o;
        }
    }

    float acc2[8][4];
    #pragma unroll
    for (int m = 0; m < 8; m++)
        { acc2[m][0]=0.f; acc2[m][1]=0.f; acc2[m][2]=0.f; acc2[m][3]=0.f; }
    for (int kc = 0; kc < 4; kc++) {
        __syncthreads();
        {
            float4* d = (float4*)(s + O2_W);
            const float4* g = (const float4*)(w2 + kc * 64 * 256);
            for (int i = tid; i < (64 * 256) / 4; i += 256) d[i] = g[i];
        }
        __syncthreads();
        const int kbase = kc * 64;
        for (int k = 0; k < 64; k++) {
            float4 w = *(const float4*)(s + O2_W + k * 256 + c0);
            #pragma unroll
            for (int m = 0; m < 8; m++) {
                float h = s[O2_H + (r0 + m) * 260 + kbase + k];
                acc2[m][0] += h * w.x; acc2[m][1] += h * w.y;
                acc2[m][2] += h * w.z; acc2[m][3] += h * w.w;
            }
        }
    }
    __syncthreads();
    {
        float4 bb = *(const float4*)(b2 + c0);
        #pragma unroll
        for (int m = 0; m < 8; m++) {
            float4 o;
            o.x = lrelu(acc2[m][0] + bb.x);
            o.y = lrelu(acc2[m][1] + bb.y);
            o.z = lrelu(acc2[m][2] + bb.z);
            o.w = lrelu(acc2[m][3] + bb.w);
            *(float4*)(s + O2_H + (r0 + m) * 260 + c0) = o;
        }
    }
    __syncthreads();

    for (int idx = tid; idx < 768; idx += 256) s[O2_W + idx] = w3[idx];
    __syncthreads();
    if (tid < 96) {
        int r = tid / 3, o = tid - r * 3;
        float a = b3[o];
        for (int k = 0; k < 256; k++)
            a += s[O2_H + r * 260 + k] * s[O2_W + k * 3 + o];
        out[(row0 + r) * 3 + o] = a;
    }
}

extern "C" void kernel_launch(void* const* d_in, const int* in_sizes, int n_in,
                              void* d_out, int out_size)
{
    const float* x    = (const float*)d_in[0];
    const float* few1 = (const float*)d_in[1];
    const float* feb1 = (const float*)d_in[2];
    const float* few2 = (const float*)d_in[3];
    const float* feb2 = (const float*)d_in[4];
    const float* few3 = (const float*)d_in[5];
    const float* feb3 = (const float*)d_in[6];
    const float* fnw1 = (const float*)d_in[7];
    const float* fnb1 = (const float*)d_in[8];
    const float* fnw2 = (const float*)d_in[9];
    const float* fnb2 = (const float*)d_in[10];
    const float* fnw3 = (const float*)d_in[11];
    const float* fnb3 = (const float*)d_in[12];
    float* out = (float*)d_out;

    cudaFuncSetAttribute(edge_kernel, cudaFuncAttributeMaxDynamicSharedMemorySize, SMEM1_BYTES);
    cudaFuncSetAttribute(node_kernel, cudaFuncAttributeMaxDynamicSharedMemorySize, SMEM2_BYTES);

    edge_kernel<<<148, 256, SMEM1_BYTES>>>(x, few1, feb1, few2, feb2, few3, feb3);
    node_kernel<<<300, 256, SMEM2_BYTES>>>(x, fnw1, fnb1, fnw2, fnb2, fnw3, fnb3, out);
}

// round 4
// speedup vs baseline: 1.0014x; 1.0014x over previous
#include <cuda_runtime.h>

#define ALPHA 0.2f

// Aggregated edge features scratch: [128*75, 192] = 7.37 MB (static, allowed)
static __device__ float g_agg[9600 * 192];

__device__ __forceinline__ float lrelu(float v) { return v > 0.0f ? v : ALPHA * v; }

// packed f32x2 FMA: acc.lo += a.lo*b.lo; acc.hi += a.hi*b.hi
#define FFMA2(acc, a, b) \
    asm("fma.rn.f32x2 %0, %1, %2, %0;" : "+l"(acc) : "l"(a), "l"(b))

__device__ __forceinline__ float2 unpack2(unsigned long long v) {
    float2 r;
    asm("mov.b64 {%0, %1}, %2;" : "=f"(r.x), "=f"(r.y) : "l"(v));
    return r;
}

// ---------------- Edge kernel: persistent CTAs, one (b,i) at a time ----------------
// SMEM layout (floats). W2/W3 stored k-pair interleaved:
//   s[O_W2 + (k2*160 + c)*2 + p] = w2[(2*k2+p)*160 + c]
#define O_W1 0        // 7*96   = 672
#define O_W2 672      // 96*160 = 15360 (paired)
#define O_W3 16032    // 160*192= 30720 (paired)
#define O_B2 46752    // 160
#define O_B3 46912    // 192
#define O_UI 47104    // 96   (b1 + x_i @ W1[0:3])
#define O_XJ 47200    // 75*3 (pad to 228)
#define O_D  47428    // 75   (pad to 76)
#define O_H1 47504    // 25 rows * stride 100 = 2500
#define O_H2 50004    // 25 rows * stride 164 = 4100
#define O_AG 54104    // 192
#define SMEM1_FL 54296
#define SMEM1_BYTES (SMEM1_FL * 4)

__global__ void __launch_bounds__(256, 1)
edge_kernel(const float* __restrict__ x,
            const float* __restrict__ w1, const float* __restrict__ b1,
            const float* __restrict__ w2, const float* __restrict__ b2,
            const float* __restrict__ w3, const float* __restrict__ b3)
{
    extern __shared__ float s[];
    const int tid = threadIdx.x;

    // ---- One-time weight load (W2/W3 permuted to k-pair layout) ----
    {
        float4* d; const float4* g;
        d = (float4*)(s + O_W1); g = (const float4*)w1;
        for (int i = tid; i < 672 / 4; i += 256) d[i] = g[i];
        for (int idx = tid; idx < 96 * 160; idx += 256) {
            int k = idx / 160, c = idx - k * 160;
            s[O_W2 + ((k >> 1) * 160 + c) * 2 + (k & 1)] = w2[idx];
        }
        for (int idx = tid; idx < 160 * 192; idx += 256) {
            int k = idx / 192, c = idx - k * 192;
            s[O_W3 + ((k >> 1) * 192 + c) * 2 + (k & 1)] = w3[idx];
        }
        d = (float4*)(s + O_B2); g = (const float4*)b2;
        for (int i = tid; i < 160 / 4; i += 256) d[i] = g[i];
        d = (float4*)(s + O_B3); g = (const float4*)b3;
        for (int i = tid; i < 192 / 4; i += 256) d[i] = g[i];
    }

    // TRANSPOSED lane mapping: rg = tid % 5 (h-row dedup within warp),
    // cg = tid / 5 (only ~7 distinct weight addrs per warp -> SMEM multicast).
    // L2: 200 threads = 40 colgroups x 5 rowgroups
    const int rg2 = tid % 5, cg2 = tid / 5;
    const int ca2 = 2 * cg2, cb2 = 80 + 2 * cg2;
    // L3: 240 threads = 48 colgroups x 5 rowgroups
    const int rg3 = tid % 5, cg3 = tid / 5;
    const int ca3 = 2 * cg3, cb3 = 96 + 2 * cg3;

    for (int bi = blockIdx.x; bi < 9600; bi += gridDim.x) {
        const int b = bi / 75, i = bi % 75;
        const float* xb = x + b * 75 * 3;
        const float xi0 = xb[i * 3 + 0], xi1 = xb[i * 3 + 1], xi2 = xb[i * 3 + 2];

        if (tid < 75) {
            float a0 = xb[tid * 3 + 0], a1 = xb[tid * 3 + 1], a2 = xb[tid * 3 + 2];
            s[O_XJ + 3 * tid + 0] = a0;
            s[O_XJ + 3 * tid + 1] = a1;
            s[O_XJ + 3 * tid + 2] = a2;
            float d0 = (a0 - xi0) + 1e-12f;
            float d1 = (a1 - xi1) + 1e-12f;
            float d2 = (a2 - xi2) + 1e-12f;
            s[O_D + tid] = sqrtf(d0 * d0 + d1 * d1 + d2 * d2);
        }
        if (tid < 192) s[O_AG + tid] = 0.0f;
        __syncthreads();   // also covers weight load on first iteration

        // U_i[c] = b1[c] + x_i @ W1[0:3, c]
        if (tid < 96)
            s[O_UI + tid] = b1[tid] + xi0 * s[O_W1 + tid]
                                    + xi1 * s[O_W1 + 96 + tid]
                                    + xi2 * s[O_W1 + 192 + tid];
        __syncthreads();

        float ag0 = 0.f, ag1 = 0.f, ag2 = 0.f, ag3 = 0.f;

        for (int t = 0; t < 3; t++) {
            const int j0 = t * 25;

            // ---- Layer 1: h1[25][96] ----
            for (int idx = tid; idx < 25 * 96; idx += 256) {
                int r = idx / 96, c = idx - r * 96;
                int j = j0 + r;
                float v = s[O_UI + c]
                        + s[O_XJ + 3 * j + 0] * s[O_W1 + 288 + c]
                        + s[O_XJ + 3 * j + 1] * s[O_W1 + 384 + c]
                        + s[O_XJ + 3 * j + 2] * s[O_W1 + 480 + c]
                        + s[O_D + j]          * s[O_W1 + 576 + c];
                s[O_H1 + r * 100 + c] = lrelu(v);
            }
            __syncthreads();

            // ---- Layer 2: h2[25][160] = lrelu(h1 @ W2 + b2), FFMA2 ----
            if (tid < 200) {
                const int r0 = rg2 * 5;
                unsigned long long acc[5][4];
                #pragma unroll
                for (int m = 0; m < 5; m++)
                    { acc[m][0]=0ULL; acc[m][1]=0ULL; acc[m][2]=0ULL; acc[m][3]=0ULL; }
                const float* h1b = s + O_H1 + r0 * 100;
                const float* w2p = s + O_W2;
                #pragma unroll 2
                for (int k2 = 0; k2 < 48; k2++) {
                    ulonglong2 wa = *(const ulonglong2*)(w2p + (k2 * 160 + ca2) * 2);
                    ulonglong2 wb = *(const ulonglong2*)(w2p + (k2 * 160 + cb2) * 2);
                    #pragma unroll
                    for (int m = 0; m < 5; m++) {
                        unsigned long long hp =
                            *(const unsigned long long*)(h1b + m * 100 + 2 * k2);
                        FFMA2(acc[m][0], hp, wa.x);
                        FFMA2(acc[m][1], hp, wa.y);
                        FFMA2(acc[m][2], hp, wb.x);
                        FFMA2(acc[m][3], hp, wb.y);
                    }
                }
                float ba0 = s[O_B2 + ca2], ba1 = s[O_B2 + ca2 + 1];
                float bb0 = s[O_B2 + cb2], bb1 = s[O_B2 + cb2 + 1];
                #pragma unroll
                for (int m = 0; m < 5; m++) {
                    float2 p0 = unpack2(acc[m][0]);
                    float2 p1 = unpack2(acc[m][1]);
                    float2 p2 = unpack2(acc[m][2]);
                    float2 p3 = unpack2(acc[m][3]);
                    float* hr = s + O_H2 + (r0 + m) * 164;
                    hr[ca2]     = lrelu(p0.x + p0.y + ba0);
                    hr[ca2 + 1] = lrelu(p1.x + p1.y + ba1);
                    hr[cb2]     = lrelu(p2.x + p2.y + bb0);
                    hr[cb2 + 1] = lrelu(p3.x + p3.y + bb1);
                }
            }
            __syncthreads();

            // ---- Layer 3 + aggregation, FFMA2 ----
            if (tid < 240) {
                const int r0 = rg3 * 5;
                unsigned long long acc[5][4];
                #pragma unroll
                for (int m = 0; m < 5; m++)
                    { acc[m][0]=0ULL; acc[m][1]=0ULL; acc[m][2]=0ULL; acc[m][3]=0ULL; }
                const float* h2b = s + O_H2 + r0 * 164;
                const float* w3p = s + O_W3;
                #pragma unroll 2
                for (int k2 = 0; k2 < 80; k2++) {
                    ulonglong2 wa = *(const ulonglong2*)(w3p + (k2 * 192 + ca3) * 2);
                    ulonglong2 wb = *(const ulonglong2*)(w3p + (k2 * 192 + cb3) * 2);
                    #pragma unroll
                    for (int m = 0; m < 5; m++) {
                        unsigned long long hp =
                            *(const unsigned long long*)(h2b + m * 164 + 2 * k2);
                        FFMA2(acc[m][0], hp, wa.x);
                        FFMA2(acc[m][1], hp, wa.y);
                        FFMA2(acc[m][2], hp, wb.x);
                        FFMA2(acc[m][3], hp, wb.y);
                    }
                }
                float ba0 = s[O_B3 + ca3], ba1 = s[O_B3 + ca3 + 1];
                float bb0 = s[O_B3 + cb3], bb1 = s[O_B3 + cb3 + 1];
                #pragma unroll
                for (int m = 0; m < 5; m++) {
                    float2 p0 = unpack2(acc[m][0]);
                    float2 p1 = unpack2(acc[m][1]);
                    float2 p2 = unpack2(acc[m][2]);
                    float2 p3 = unpack2(acc[m][3]);
                    ag0 += lrelu(p0.x + p0.y + ba0);
                    ag1 += lrelu(p1.x + p1.y + ba1);
                    ag2 += lrelu(p2.x + p2.y + bb0);
                    ag3 += lrelu(p3.x + p3.y + bb1);
                }
            }
            __syncthreads();   // protect H1/H2 before next tile overwrites
        }

        if (tid < 240) {
            atomicAdd(&s[O_AG + ca3],     ag0);
            atomicAdd(&s[O_AG + ca3 + 1], ag1);
            atomicAdd(&s[O_AG + cb3],     ag2);
            atomicAdd(&s[O_AG + cb3 + 1], ag3);
        }
        __syncthreads();
        if (tid < 192) g_agg[bi * 192 + tid] = s[O_AG + tid];
        __syncthreads();   // O_AG/O_XJ reused next iteration
    }
}

// ---------------- Node kernel: one CTA per 32 rows (unchanged) ----------------
#define O2_Y 0         // 32 * 200 = 6400 (195 used)
#define O2_H 6400      // 32 * 260 = 8320
#define O2_W 14720     // up to 65*256 = 16640
#define SMEM2_FL 31360
#define SMEM2_BYTES (SMEM2_FL * 4)

__global__ void __launch_bounds__(256, 1)
node_kernel(const float* __restrict__ x,
            const float* __restrict__ w1, const float* __restrict__ b1,
            const float* __restrict__ w2, const float* __restrict__ b2,
            const float* __restrict__ w3, const float* __restrict__ b3,
            float* __restrict__ out)
{
    extern __shared__ float s[];
    const int tid = threadIdx.x;
    const int row0 = blockIdx.x * 32;

    for (int idx = tid; idx < 32 * 192; idx += 256) {
        int r = idx / 192, c = idx - r * 192;
        s[O2_Y + r * 200 + c] = g_agg[(row0 + r) * 192 + c];
    }
    for (int idx = tid; idx < 96; idx += 256) {
        int r = idx / 3, c = idx - r * 3;
        s[O2_Y + r * 200 + 192 + c] = x[(row0 + r) * 3 + c];
    }

    const int cg = tid % 64, rg = tid / 64;
    const int c0 = cg * 4, r0 = rg * 8;

    float acc[8][4];
    #pragma unroll
    for (int m = 0; m < 8; m++)
        { acc[m][0]=0.f; acc[m][1]=0.f; acc[m][2]=0.f; acc[m][3]=0.f; }
    for (int kc = 0; kc < 3; kc++) {
        __syncthreads();
        {
            float4* d = (float4*)(s + O2_W);
            const float4* g = (const float4*)(w1 + kc * 65 * 256);
            for (int i = tid; i < (65 * 256) / 4; i += 256) d[i] = g[i];
        }
        __syncthreads();
        const int kbase = kc * 65;
        for (int k = 0; k < 65; k++) {
            float4 w = *(const float4*)(s + O2_W + k * 256 + c0);
            #pragma unroll
            for (int m = 0; m < 8; m++) {
                float h = s[O2_Y + (r0 + m) * 200 + kbase + k];
                acc[m][0] += h * w.x; acc[m][1] += h * w.y;
                acc[m][2] += h * w.z; acc[m][3] += h * w.w;
            }
        }
    }
    __syncthreads();
    {
        float4 bb = *(const float4*)(b1 + c0);
        #pragma unroll
        for (int m = 0; m < 8; m++) {
            float4 o;
            o.x = lrelu(acc[m][0] + bb.x);
            o.y = lrelu(acc[m][1] + bb.y);
            o.z = lrelu(acc[m][2] + bb.z);
            o.w = lrelu(acc[m][3] + bb.w);
            *(float4*)(s + O2_H + (r0 + m) * 260 + c0) = o;
        }
    }

    float acc2[8][4];
    #pragma unroll
    for (int m = 0; m < 8; m++)
        { acc2[m][0]=0.f; acc2[m][1]=0.f; acc2[m][2]=0.f; acc2[m][3]=0.f; }
    for (int kc = 0; kc < 4; kc++) {
        __syncthreads();
        {
            float4* d = (float4*)(s + O2_W);
            const float4* g = (const float4*)(w2 + kc * 64 * 256);
            for (int i = tid; i < (64 * 256) / 4; i += 256) d[i] = g[i];
        }
        __syncthreads();
        const int kbase = kc * 64;
        for (int k = 0; k < 64; k++) {
            float4 w = *(const float4*)(s + O2_W + k * 256 + c0);
            #pragma unroll
            for (int m = 0; m < 8; m++) {
                float h = s[O2_H + (r0 + m) * 260 + kbase + k];
                acc2[m][0] += h * w.x; acc2[m][1] += h * w.y;
                acc2[m][2] += h * w.z; acc2[m][3] += h * w.w;
            }
        }
    }
    __syncthreads();
    {
        float4 bb = *(const float4*)(b2 + c0);
        #pragma unroll
        for (int m = 0; m < 8; m++) {
            float4 o;
            o.x = lrelu(acc2[m][0] + bb.x);
            o.y = lrelu(acc2[m][1] + bb.y);
            o.z = lrelu(acc2[m][2] + bb.z);
            o.w = lrelu(acc2[m][3] + bb.w);
            *(float4*)(s + O2_H + (r0 + m) * 260 + c0) = o;
        }
    }
    __syncthreads();

    for (int idx = tid; idx < 768; idx += 256) s[O2_W + idx] = w3[idx];
    __syncthreads();
    if (tid < 96) {
        int r = tid / 3, o = tid - r * 3;
        float a = b3[o];
        for (int k = 0; k < 256; k++)
            a += s[O2_H + r * 260 + k] * s[O2_W + k * 3 + o];
        out[(row0 + r) * 3 + o] = a;
    }
}

extern "C" void kernel_launch(void* const* d_in, const int* in_sizes, int n_in,
                              void* d_out, int out_size)
{
    const float* x    = (const float*)d_in[0];
    const float* few1 = (const float*)d_in[1];
    const float* feb1 = (const float*)d_in[2];
    const float* few2 = (const float*)d_in[3];
    const float* feb2 = (const float*)d_in[4];
    const float* few3 = (const float*)d_in[5];
    const float* feb3 = (const float*)d_in[6];
    const float* fnw1 = (const float*)d_in[7];
    const float* fnb1 = (const float*)d_in[8];
    const float* fnw2 = (const float*)d_in[9];
    const float* fnb2 = (const float*)d_in[10];
    const float* fnw3 = (const float*)d_in[11];
    const float* fnb3 = (const float*)d_in[12];
    float* out = (float*)d_out;

    cudaFuncSetAttribute(edge_kernel, cudaFuncAttributeMaxDynamicSharedMemorySize, SMEM1_BYTES);
    cudaFuncSetAttribute(node_kernel, cudaFuncAttributeMaxDynamicSharedMemorySize, SMEM2_BYTES);

    edge_kernel<<<148, 256, SMEM1_BYTES>>>(x, few1, feb1, few2, feb2, few3, feb3);
    node_kernel<<<300, 256, SMEM2_BYTES>>>(x, fnw1, fnb1, fnw2, fnb2, fnw3, fnb3, out);
}

// round 5
// speedup vs baseline: 1.2344x; 1.2327x over previous
#include <cuda_runtime.h>

#define ALPHA 0.2f

// Aggregated edge features scratch: [128*75, 192] = 7.37 MB (static, allowed)
static __device__ float g_agg[9600 * 192];

__device__ __forceinline__ float lrelu(float v) { return v > 0.0f ? v : ALPHA * v; }

// packed f32x2 FMA: acc.lo += a.lo*b.lo; acc.hi += a.hi*b.hi
#define FFMA2(acc, a, b) \
    asm("fma.rn.f32x2 %0, %1, %2, %0;" : "+l"(acc) : "l"(a), "l"(b))

__device__ __forceinline__ float2 unpack2(unsigned long long v) {
    float2 r;
    asm("mov.b64 {%0, %1}, %2;" : "=f"(r.x), "=f"(r.y) : "l"(v));
    return r;
}
__device__ __forceinline__ unsigned long long pack2(float lo, float hi) {
    unsigned long long r;
    asm("mov.b64 %0, {%1, %2};" : "=l"(r) : "f"(lo), "f"(hi));
    return r;
}

// ---------------- Edge kernel: persistent CTAs, one (b,i) at a time ----------------
// SMEM layout (floats). W2/W3 stored k-pair interleaved:
//   s[O_W2 + (k2*160 + c)*2 + p] = w2[(2*k2+p)*160 + c]
#define O_W1 0        // 7*96   = 672
#define O_W2 672      // 96*160 = 15360 (paired)
#define O_W3 16032    // 160*192= 30720 (paired)
#define O_B2 46752    // 160
#define O_B3 46912    // 192
#define O_UI 47104    // 96   (b1 + x_i @ W1[0:3])
#define O_XJ 47200    // 75*3 (pad to 228)
#define O_D  47428    // 75   (pad to 76)
#define O_H1 47504    // 25 rows * stride 100 = 2500
#define O_H2 50004    // 25 rows * stride 164 = 4100
#define O_AG 54104    // 192
#define SMEM1_FL 54296
#define SMEM1_BYTES (SMEM1_FL * 4)

__global__ void __launch_bounds__(256, 1)
edge_kernel(const float* __restrict__ x,
            const float* __restrict__ w1, const float* __restrict__ b1,
            const float* __restrict__ w2, const float* __restrict__ b2,
            const float* __restrict__ w3, const float* __restrict__ b3)
{
    extern __shared__ float s[];
    const int tid = threadIdx.x;

    // ---- One-time weight load (W2/W3 permuted to k-pair layout) ----
    {
        float4* d; const float4* g;
        d = (float4*)(s + O_W1); g = (const float4*)w1;
        for (int i = tid; i < 672 / 4; i += 256) d[i] = g[i];
        for (int idx = tid; idx < 96 * 160; idx += 256) {
            int k = idx / 160, c = idx - k * 160;
            s[O_W2 + ((k >> 1) * 160 + c) * 2 + (k & 1)] = w2[idx];
        }
        for (int idx = tid; idx < 160 * 192; idx += 256) {
            int k = idx / 192, c = idx - k * 192;
            s[O_W3 + ((k >> 1) * 192 + c) * 2 + (k & 1)] = w3[idx];
        }
        d = (float4*)(s + O_B2); g = (const float4*)b2;
        for (int i = tid; i < 160 / 4; i += 256) d[i] = g[i];
        d = (float4*)(s + O_B3); g = (const float4*)b3;
        for (int i = tid; i < 192 / 4; i += 256) d[i] = g[i];
    }
    __syncthreads();   // weights resident for whole persistent loop

    // R2 (proven-fast) lane mapping: cg fast-varying -> h broadcast per warp.
    // L2: 200 threads = 40 colgroups x 5 rowgroups
    const int cg2 = tid % 40, rg2 = tid / 40;
    const int ca2 = 2 * cg2, cb2 = 80 + 2 * cg2;
    // L3: 240 threads = 48 colgroups x 5 rowgroups
    const int cg3 = tid % 48, rg3 = tid / 48;
    const int ca3 = 2 * cg3, cb3 = 96 + 2 * cg3;

    for (int bi = blockIdx.x; bi < 9600; bi += gridDim.x) {
        const int b = bi / 75, i = bi % 75;
        const float* xb = x + b * 75 * 3;
        const float xi0 = xb[i * 3 + 0], xi1 = xb[i * 3 + 1], xi2 = xb[i * 3 + 2];

        // Phase A (single barrier): XJ/D by tid<75, AG zero by tid<192,
        // U_i by tid in [160,256) (reads W1 which is loop-invariant).
        if (tid < 75) {
            float a0 = xb[tid * 3 + 0], a1 = xb[tid * 3 + 1], a2 = xb[tid * 3 + 2];
            s[O_XJ + 3 * tid + 0] = a0;
            s[O_XJ + 3 * tid + 1] = a1;
            s[O_XJ + 3 * tid + 2] = a2;
            float d0 = (a0 - xi0) + 1e-12f;
            float d1 = (a1 - xi1) + 1e-12f;
            float d2 = (a2 - xi2) + 1e-12f;
            s[O_D + tid] = sqrtf(d0 * d0 + d1 * d1 + d2 * d2);
        }
        if (tid < 192) s[O_AG + tid] = 0.0f;
        if (tid >= 160) {
            int c = tid - 160;   // 0..95
            s[O_UI + c] = b1[c] + xi0 * s[O_W1 + c]
                                + xi1 * s[O_W1 + 96 + c]
                                + xi2 * s[O_W1 + 192 + c];
        }
        __syncthreads();

        float ag0 = 0.f, ag1 = 0.f, ag2 = 0.f, ag3 = 0.f;

        for (int t = 0; t < 3; t++) {
            const int j0 = t * 25;

            // ---- Layer 1 (FFMA2 over column pairs): h1[25][96] ----
            for (int idx = tid; idx < 25 * 48; idx += 256) {
                int r = idx / 48, c2 = idx - r * 48;
                int j = j0 + r;
                float xj0 = s[O_XJ + 3 * j + 0];
                float xj1 = s[O_XJ + 3 * j + 1];
                float xj2 = s[O_XJ + 3 * j + 2];
                float dj  = s[O_D + j];
                unsigned long long v =
                    *(const unsigned long long*)(s + O_UI + 2 * c2);
                unsigned long long w, p;
                p = pack2(xj0, xj0);
                w = *(const unsigned long long*)(s + O_W1 + 288 + 2 * c2);
                FFMA2(v, p, w);
                p = pack2(xj1, xj1);
                w = *(const unsigned long long*)(s + O_W1 + 384 + 2 * c2);
                FFMA2(v, p, w);
                p = pack2(xj2, xj2);
                w = *(const unsigned long long*)(s + O_W1 + 480 + 2 * c2);
                FFMA2(v, p, w);
                p = pack2(dj, dj);
                w = *(const unsigned long long*)(s + O_W1 + 576 + 2 * c2);
                FFMA2(v, p, w);
                float2 vf = unpack2(v);
                *(float2*)(s + O_H1 + r * 100 + 2 * c2) =
                    make_float2(lrelu(vf.x), lrelu(vf.y));
            }
            __syncthreads();

            // ---- Layer 2: h2[25][160] = lrelu(h1 @ W2 + b2), FFMA2 ----
            if (tid < 200) {
                const int r0 = rg2 * 5;
                unsigned long long acc[5][4];
                #pragma unroll
                for (int m = 0; m < 5; m++)
                    { acc[m][0]=0ULL; acc[m][1]=0ULL; acc[m][2]=0ULL; acc[m][3]=0ULL; }
                const float* h1b = s + O_H1 + r0 * 100;
                const float* w2p = s + O_W2;
                #pragma unroll 4
                for (int k2 = 0; k2 < 48; k2++) {
                    ulonglong2 wa = *(const ulonglong2*)(w2p + (k2 * 160 + ca2) * 2);
                    ulonglong2 wb = *(const ulonglong2*)(w2p + (k2 * 160 + cb2) * 2);
                    #pragma unroll
                    for (int m = 0; m < 5; m++) {
                        unsigned long long hp =
                            *(const unsigned long long*)(h1b + m * 100 + 2 * k2);
                        FFMA2(acc[m][0], hp, wa.x);
                        FFMA2(acc[m][1], hp, wa.y);
                        FFMA2(acc[m][2], hp, wb.x);
                        FFMA2(acc[m][3], hp, wb.y);
                    }
                }
                float ba0 = s[O_B2 + ca2], ba1 = s[O_B2 + ca2 + 1];
                float bb0 = s[O_B2 + cb2], bb1 = s[O_B2 + cb2 + 1];
                #pragma unroll
                for (int m = 0; m < 5; m++) {
                    float2 p0 = unpack2(acc[m][0]);
                    float2 p1 = unpack2(acc[m][1]);
                    float2 p2 = unpack2(acc[m][2]);
                    float2 p3 = unpack2(acc[m][3]);
                    float* hr = s + O_H2 + (r0 + m) * 164;
                    hr[ca2]     = lrelu(p0.x + p0.y + ba0);
                    hr[ca2 + 1] = lrelu(p1.x + p1.y + ba1);
                    hr[cb2]     = lrelu(p2.x + p2.y + bb0);
                    hr[cb2 + 1] = lrelu(p3.x + p3.y + bb1);
                }
            }
            __syncthreads();

            // ---- Layer 3 + aggregation, FFMA2 (no trailing barrier:
            //      post-L1 sync of next tile fences H2 reuse; H1 writes
            //      were already fenced by the post-L2 sync) ----
            if (tid < 240) {
                const int r0 = rg3 * 5;
                unsigned long long acc[5][4];
                #pragma unroll
                for (int m = 0; m < 5; m++)
                    { acc[m][0]=0ULL; acc[m][1]=0ULL; acc[m][2]=0ULL; acc[m][3]=0ULL; }
                const float* h2b = s + O_H2 + r0 * 164;
                const float* w3p = s + O_W3;
                #pragma unroll 4
                for (int k2 = 0; k2 < 80; k2++) {
                    ulonglong2 wa = *(const ulonglong2*)(w3p + (k2 * 192 + ca3) * 2);
                    ulonglong2 wb = *(const ulonglong2*)(w3p + (k2 * 192 + cb3) * 2);
                    #pragma unroll
                    for (int m = 0; m < 5; m++) {
                        unsigned long long hp =
                            *(const unsigned long long*)(h2b + m * 164 + 2 * k2);
                        FFMA2(acc[m][0], hp, wa.x);
                        FFMA2(acc[m][1], hp, wa.y);
                        FFMA2(acc[m][2], hp, wb.x);
                        FFMA2(acc[m][3], hp, wb.y);
                    }
                }
                float ba0 = s[O_B3 + ca3], ba1 = s[O_B3 + ca3 + 1];
                float bb0 = s[O_B3 + cb3], bb1 = s[O_B3 + cb3 + 1];
                #pragma unroll
                for (int m = 0; m < 5; m++) {
                    float2 p0 = unpack2(acc[m][0]);
                    float2 p1 = unpack2(acc[m][1]);
                    float2 p2 = unpack2(acc[m][2]);
                    float2 p3 = unpack2(acc[m][3]);
                    ag0 += lrelu(p0.x + p0.y + ba0);
                    ag1 += lrelu(p1.x + p1.y + ba1);
                    ag2 += lrelu(p2.x + p2.y + bb0);
                    ag3 += lrelu(p3.x + p3.y + bb1);
                }
            }
        }

        if (tid < 240) {
            atomicAdd(&s[O_AG + ca3],     ag0);
            atomicAdd(&s[O_AG + ca3 + 1], ag1);
            atomicAdd(&s[O_AG + cb3],     ag2);
            atomicAdd(&s[O_AG + cb3 + 1], ag3);
        }
        __syncthreads();
        if (tid < 192) g_agg[bi * 192 + tid] = s[O_AG + tid];
        __syncthreads();   // O_AG/O_XJ/O_UI reused next iteration
    }
}

// ---------------- Node kernel: one CTA per 32 rows (unchanged) ----------------
#define O2_Y 0         // 32 * 200 = 6400 (195 used)
#define O2_H 6400      // 32 * 260 = 8320
#define O2_W 14720     // up to 65*256 = 16640
#define SMEM2_FL 31360
#define SMEM2_BYTES (SMEM2_FL * 4)

__global__ void __launch_bounds__(256, 1)
node_kernel(const float* __restrict__ x,
            const float* __restrict__ w1, const float* __restrict__ b1,
            const float* __restrict__ w2, const float* __restrict__ b2,
            const float* __restrict__ w3, const float* __restrict__ b3,
            float* __restrict__ out)
{
    extern __shared__ float s[];
    const int tid = threadIdx.x;
    const int row0 = blockIdx.x * 32;

    for (int idx = tid; idx < 32 * 192; idx += 256) {
        int r = idx / 192, c = idx - r * 192;
        s[O2_Y + r * 200 + c] = g_agg[(row0 + r) * 192 + c];
    }
    for (int idx = tid; idx < 96; idx += 256) {
        int r = idx / 3, c = idx - r * 3;
        s[O2_Y + r * 200 + 192 + c] = x[(row0 + r) * 3 + c];
    }

    const int cg = tid % 64, rg = tid / 64;
    const int c0 = cg * 4, r0 = rg * 8;

    float acc[8][4];
    #pragma unroll
    for (int m = 0; m < 8; m++)
        { acc[m][0]=0.f; acc[m][1]=0.f; acc[m][2]=0.f; acc[m][3]=0.f; }
    for (int kc = 0; kc < 3; kc++) {
        __syncthreads();
        {
            float4* d = (float4*)(s + O2_W);
            const float4* g = (const float4*)(w1 + kc * 65 * 256);
            for (int i = tid; i < (65 * 256) / 4; i += 256) d[i] = g[i];
        }
        __syncthreads();
        const int kbase = kc * 65;
        for (int k = 0; k < 65; k++) {
            float4 w = *(const float4*)(s + O2_W + k * 256 + c0);
            #pragma unroll
            for (int m = 0; m < 8; m++) {
                float h = s[O2_Y + (r0 + m) * 200 + kbase + k];
                acc[m][0] += h * w.x; acc[m][1] += h * w.y;
                acc[m][2] += h * w.z; acc[m][3] += h * w.w;
            }
        }
    }
    __syncthreads();
    {
        float4 bb = *(const float4*)(b1 + c0);
        #pragma unroll
        for (int m = 0; m < 8; m++) {
            float4 o;
            o.x = lrelu(acc[m][0] + bb.x);
            o.y = lrelu(acc[m][1] + bb.y);
            o.z = lrelu(acc[m][2] + bb.z);
            o.w = lrelu(acc[m][3] + bb.w);
            *(float4*)(s + O2_H + (r0 + m) * 260 + c0) = o;
        }
    }

    float acc2[8][4];
    #pragma unroll
    for (int m = 0; m < 8; m++)
        { acc2[m][0]=0.f; acc2[m][1]=0.f; acc2[m][2]=0.f; acc2[m][3]=0.f; }
    for (int kc = 0; kc < 4; kc++) {
        __syncthreads();
        {
            float4* d = (float4*)(s + O2_W);
            const float4* g = (const float4*)(w2 + kc * 64 * 256);
            for (int i = tid; i < (64 * 256) / 4; i += 256) d[i] = g[i];
        }
        __syncthreads();
        const int kbase = kc * 64;
        for (int k = 0; k < 64; k++) {
            float4 w = *(const float4*)(s + O2_W + k * 256 + c0);
            #pragma unroll
            for (int m = 0; m < 8; m++) {
                float h = s[O2_H + (r0 + m) * 260 + kbase + k];
                acc2[m][0] += h * w.x; acc2[m][1] += h * w.y;
                acc2[m][2] += h * w.z; acc2[m][3] += h * w.w;
            }
        }
    }
    __syncthreads();
    {
        float4 bb = *(const float4*)(b2 + c0);
        #pragma unroll
        for (int m = 0; m < 8; m++) {
            float4 o;
            o.x = lrelu(acc2[m][0] + bb.x);
            o.y = lrelu(acc2[m][1] + bb.y);
            o.z = lrelu(acc2[m][2] + bb.z);
            o.w = lrelu(acc2[m][3] + bb.w);
            *(float4*)(s + O2_H + (r0 + m) * 260 + c0) = o;
        }
    }
    __syncthreads();

    for (int idx = tid; idx < 768; idx += 256) s[O2_W + idx] = w3[idx];
    __syncthreads();
    if (tid < 96) {
        int r = tid / 3, o = tid - r * 3;
        float a = b3[o];
        for (int k = 0; k < 256; k++)
            a += s[O2_H + r * 260 + k] * s[O2_W + k * 3 + o];
        out[(row0 + r) * 3 + o] = a;
    }
}

extern "C" void kernel_launch(void* const* d_in, const int* in_sizes, int n_in,
                              void* d_out, int out_size)
{
    const float* x    = (const float*)d_in[0];
    const float* few1 = (const float*)d_in[1];
    const float* feb1 = (const float*)d_in[2];
    const float* few2 = (const float*)d_in[3];
    const float* feb2 = (const float*)d_in[4];
    const float* few3 = (const float*)d_in[5];
    const float* feb3 = (const float*)d_in[6];
    const float* fnw1 = (const float*)d_in[7];
    const float* fnb1 = (const float*)d_in[8];
    const float* fnw2 = (const float*)d_in[9];
    const float* fnb2 = (const float*)d_in[10];
    const float* fnw3 = (const float*)d_in[11];
    const float* fnb3 = (const float*)d_in[12];
    float* out = (float*)d_out;

    cudaFuncSetAttribute(edge_kernel, cudaFuncAttributeMaxDynamicSharedMemorySize, SMEM1_BYTES);
    cudaFuncSetAttribute(node_kernel, cudaFuncAttributeMaxDynamicSharedMemorySize, SMEM2_BYTES);

    edge_kernel<<<148, 256, SMEM1_BYTES>>>(x, few1, feb1, few2, feb2, few3, feb3);
    node_kernel<<<300, 256, SMEM2_BYTES>>>(x, fnw1, fnb1, fnw2, fnb2, fnw3, fnb3, out);
}

// round 7
// speedup vs baseline: 5.9343x; 4.8073x over previous
#include <cuda_runtime.h>
#include <cuda_fp16.h>
#include <cstdint>

#define ALPHA 0.2f

// Aggregated edge features scratch: [128*75, 192] = 7.37 MB (static, allowed)
static __device__ float g_agg[9600 * 192];

__device__ __forceinline__ float lrelu(float v) { return v > 0.0f ? v : ALPHA * v; }

// ---- packed fp32 helpers ----
#define FFMA2(acc, a, b) \
    asm("fma.rn.f32x2 %0, %1, %2, %0;" : "+l"(acc) : "l"(a), "l"(b))
__device__ __forceinline__ float2 unpack2(unsigned long long v) {
    float2 r;
    asm("mov.b64 {%0, %1}, %2;" : "=f"(r.x), "=f"(r.y) : "l"(v));
    return r;
}
__device__ __forceinline__ unsigned long long pack2(float lo, float hi) {
    unsigned long long r;
    asm("mov.b64 %0, {%1, %2};" : "=l"(r) : "f"(lo), "f"(hi));
    return r;
}
// pack two f32 -> f16x2 word: halves[0] = lo, halves[1] = hi
__device__ __forceinline__ uint32_t cvt_f16x2(float hi, float lo) {
    uint32_t d;
    asm("cvt.rn.f16x2.f32 %0, %1, %2;" : "=r"(d) : "f"(hi), "f"(lo));
    return d;
}
__device__ __forceinline__ uint32_t smem_u32(const void* p) {
    uint32_t a;
    asm("{ .reg .u64 t; cvta.to.shared.u64 t, %1; cvt.u32.u64 %0, t; }"
        : "=r"(a) : "l"(p));
    return a;
}

// ---- warp-level tensor core (sm_80+ path; valid on plain sm_103) ----
#define LDSM_X4(a0, a1, a2, a3, addr) \
    asm volatile("ldmatrix.sync.aligned.m8n8.x4.shared.b16 {%0,%1,%2,%3}, [%4];" \
                 : "=r"(a0), "=r"(a1), "=r"(a2), "=r"(a3) : "r"(addr))
#define LDSM_X2T(b0, b1, addr) \
    asm volatile("ldmatrix.sync.aligned.m8n8.x2.trans.shared.b16 {%0,%1}, [%2];" \
                 : "=r"(b0), "=r"(b1) : "r"(addr))
#define MMA16816(c, a0, a1, a2, a3, b0, b1) \
    asm volatile("mma.sync.aligned.m16n8k16.row.col.f32.f16.f16.f32 " \
                 "{%0,%1,%2,%3}, {%4,%5,%6,%7}, {%8,%9}, {%0,%1,%2,%3};" \
                 : "+f"((c)[0]), "+f"((c)[1]), "+f"((c)[2]), "+f"((c)[3]) \
                 : "r"(a0), "r"(a1), "r"(a2), "r"(a3), "r"(b0), "r"(b1))

// ---------------- SMEM layout ----------------
// byte regions (16B aligned; ldmatrix row strides conflict-free: mod 128 -> full perm)
#define BW2 0        // W2 fp16 [96 k][168 n-stride]  (160 used)  = 32256 B
#define BW3 32256    // W3 fp16 [160 k][200 n-stride] (192 used)  = 64000 B
#define BH1 96256    // h1 fp16 [80 m][104 k-stride]  (96 used)   = 16640 B
#define BH2 112896   // h2 fp16 [80 m][168 k-stride]  (160 used)  = 26880 B
// f32 region (index in floats)
#define OF_W1 34944  // 672
#define OF_B2 35616  // 160
#define OF_B3 35776  // 192
#define OF_UI 35968  // 96
#define OF_XJ 36064  // 228
#define OF_D  36292  // 76
#define SMEM1_FL 36368
#define SMEM1_BYTES (SMEM1_FL * 4)
// u32 views
#define H1B32 (BH1 / 4)
#define H2B32 (BH2 / 4)

__global__ void __launch_bounds__(256, 1)
edge_kernel(const float* __restrict__ x,
            const float* __restrict__ w1, const float* __restrict__ b1,
            const float* __restrict__ w2, const float* __restrict__ b2,
            const float* __restrict__ w3, const float* __restrict__ b3)
{
    extern __shared__ float s[];
    uint32_t* s32 = (uint32_t*)s;
    __half* sh = (__half*)s;
    const int tid = threadIdx.x;
    const int wid = tid >> 5;
    const int lane = tid & 31;
    const uint32_t sbase = smem_u32(s);

    // ---- one-time init ----
    for (int i = tid; i < 672; i += 256) s[OF_W1 + i] = w1[i];
    for (int i = tid; i < 160; i += 256) s[OF_B2 + i] = b2[i];
    for (int i = tid; i < 192; i += 256) s[OF_B3 + i] = b3[i];
    for (int idx = tid; idx < 96 * 160; idx += 256) {
        int k = idx / 160, n = idx - k * 160;
        sh[k * 168 + n] = __float2half(w2[idx]);
    }
    for (int idx = tid; idx < 160 * 192; idx += 256) {
        int k = idx / 192, n = idx - k * 192;
        sh[BW3 / 2 + k * 200 + n] = __float2half(w3[idx]);
    }
    // zero h1 pad rows 75..79 (never rewritten)
    for (int idx = tid; idx < 5 * 52; idx += 256)
        s32[H1B32 + (75 + idx / 52) * 52 + (idx % 52)] = 0u;
    __syncthreads();

    // ---- per-warp constants ----
    // n-tiles: warp w handles n0 = 8w, 8w+64, 8w+128 (MMA1 valid <160, MMA2 all <192)
    const int nt1 = (wid < 4) ? 3 : 2;
    int n1[3], n2[3];
    #pragma unroll
    for (int j = 0; j < 3; j++) { n1[j] = 8 * wid + 64 * j; n2[j] = 8 * wid + 64 * j; }
    const int lA = lane & 15, gA = lane >> 4;       // ldmatrix A lane mapping
    const int lB = lane & 15;                        // ldmatrix B lane mapping
    const int qr = lane >> 2, qc = lane & 3;         // C frag: row l/4, colpair l%4
    // A-frag base addresses (bytes)
    const uint32_t a1base = sbase + BH1 + (uint32_t)(lA * 104 + gA * 8) * 2;
    const uint32_t a2base = sbase + BH2 + (uint32_t)(lA * 168 + gA * 8) * 2;
    const uint32_t b2base = sbase + BW2 + (uint32_t)(lB * 168) * 2;
    const uint32_t b3base = sbase + BW3 + (uint32_t)(lB * 200) * 2;
    // epilogue biases (fixed cols per warp)
    float e1b0[3], e1b1[3], e2b0[3], e2b1[3];
    #pragma unroll
    for (int j = 0; j < 3; j++) {
        if (j < nt1) {
            e1b0[j] = s[OF_B2 + n1[j] + 2 * qc];
            e1b1[j] = s[OF_B2 + n1[j] + 2 * qc + 1];
        } else { e1b0[j] = 0.f; e1b1[j] = 0.f; }
        e2b0[j] = s[OF_B3 + n2[j] + 2 * qc];
        e2b1[j] = s[OF_B3 + n2[j] + 2 * qc + 1];
    }

    for (int bi = blockIdx.x; bi < 9600; bi += gridDim.x) {
        const int b = bi / 75, i = bi % 75;
        const float* xb = x + b * 75 * 3;
        const float xi0 = xb[i * 3 + 0], xi1 = xb[i * 3 + 1], xi2 = xb[i * 3 + 2];

        // ---- Phase A ----
        if (tid < 75) {
            float a0 = xb[tid * 3 + 0], a1 = xb[tid * 3 + 1], a2 = xb[tid * 3 + 2];
            s[OF_XJ + 3 * tid + 0] = a0;
            s[OF_XJ + 3 * tid + 1] = a1;
            s[OF_XJ + 3 * tid + 2] = a2;
            float d0 = (a0 - xi0) + 1e-12f;
            float d1 = (a1 - xi1) + 1e-12f;
            float d2 = (a2 - xi2) + 1e-12f;
            s[OF_D + tid] = sqrtf(d0 * d0 + d1 * d1 + d2 * d2);
        }
        if (tid >= 160) {
            int c = tid - 160;
            s[OF_UI + c] = b1[c] + xi0 * s[OF_W1 + c]
                                 + xi1 * s[OF_W1 + 96 + c]
                                 + xi2 * s[OF_W1 + 192 + c];
        }
        __syncthreads();

        // ---- Phase B: h1[75][96] fp16 ----
        for (int idx = tid; idx < 75 * 48; idx += 256) {
            int r = idx / 48, w = idx - r * 48;
            float xj0 = s[OF_XJ + 3 * r + 0];
            float xj1 = s[OF_XJ + 3 * r + 1];
            float xj2 = s[OF_XJ + 3 * r + 2];
            float dj  = s[OF_D + r];
            unsigned long long v = *(const unsigned long long*)(s + OF_UI + 2 * w);
            FFMA2(v, pack2(xj0, xj0), *(const unsigned long long*)(s + OF_W1 + 288 + 2 * w));
            FFMA2(v, pack2(xj1, xj1), *(const unsigned long long*)(s + OF_W1 + 384 + 2 * w));
            FFMA2(v, pack2(xj2, xj2), *(const unsigned long long*)(s + OF_W1 + 480 + 2 * w));
            FFMA2(v, pack2(dj, dj),   *(const unsigned long long*)(s + OF_W1 + 576 + 2 * w));
            float2 vf = unpack2(v);
            s32[H1B32 + r * 52 + w] = cvt_f16x2(lrelu(vf.y), lrelu(vf.x));
        }
        __syncthreads();

        // ---- MMA1: D1[80][160] = h1[80][96] @ W2 ; epi -> h2 fp16 ----
        {
            float acc[5][3][4];
            #pragma unroll
            for (int m = 0; m < 5; m++)
                #pragma unroll
                for (int j = 0; j < 3; j++)
                    { acc[m][j][0]=0.f; acc[m][j][1]=0.f; acc[m][j][2]=0.f; acc[m][j][3]=0.f; }
            #pragma unroll
            for (int k = 0; k < 6; k++) {
                uint32_t bf[3][2];
                #pragma unroll
                for (int j = 0; j < 3; j++)
                    if (j < nt1) { LDSM_X2T(bf[j][0], bf[j][1], b2base + k * 5376 + n1[j] * 2); }
                #pragma unroll
                for (int m = 0; m < 5; m++) {
                    uint32_t a0, a1, a2, a3;
                    LDSM_X4(a0, a1, a2, a3, a1base + m * 3328 + k * 32);
                    #pragma unroll
                    for (int j = 0; j < 3; j++)
                        if (j < nt1) MMA16816(acc[m][j], a0, a1, a2, a3, bf[j][0], bf[j][1]);
                }
            }
            // epilogue 1: lrelu(acc + b2) -> h2 (all rows incl. pad; masked later)
            #pragma unroll
            for (int m = 0; m < 5; m++) {
                int r1 = m * 16 + qr, r2 = r1 + 8;
                #pragma unroll
                for (int j = 0; j < 3; j++)
                    if (j < nt1) {
                        uint32_t u = n1[j] / 2 + qc;
                        s32[H2B32 + r1 * 84 + u] =
                            cvt_f16x2(lrelu(acc[m][j][1] + e1b1[j]),
                                      lrelu(acc[m][j][0] + e1b0[j]));
                        s32[H2B32 + r2 * 84 + u] =
                            cvt_f16x2(lrelu(acc[m][j][3] + e1b1[j]),
                                      lrelu(acc[m][j][2] + e1b0[j]));
                    }
            }
        }
        __syncthreads();

        // ---- MMA2: D2[80][192] = h2[80][160] @ W3 ; epi -> column sums ----
        {
            float cs0[3] = {0.f, 0.f, 0.f}, cs1[3] = {0.f, 0.f, 0.f};
            #pragma unroll
            for (int m = 0; m < 5; m++) {
                float acc[3][4];
                #pragma unroll
                for (int j = 0; j < 3; j++)
                    { acc[j][0]=0.f; acc[j][1]=0.f; acc[j][2]=0.f; acc[j][3]=0.f; }
                #pragma unroll
                for (int k = 0; k < 10; k++) {
                    uint32_t a0, a1, a2, a3;
                    LDSM_X4(a0, a1, a2, a3, a2base + m * 5376 + k * 32);
                    #pragma unroll
                    for (int j = 0; j < 3; j++) {
                        uint32_t b0, b1;
                        LDSM_X2T(b0, b1, b3base + k * 6400 + n2[j] * 2);
                        MMA16816(acc[j], a0, a1, a2, a3, b0, b1);
                    }
                }
                // accumulate lrelu(acc + b3) into column sums (mask rows >= 75)
                bool ok2 = (m * 16 + 8 + qr) < 75;   // row1 = m*16+qr always < 75
                #pragma unroll
                for (int j = 0; j < 3; j++) {
                    cs0[j] += lrelu(acc[j][0] + e2b0[j]);
                    cs1[j] += lrelu(acc[j][1] + e2b1[j]);
                    if (ok2) {
                        cs0[j] += lrelu(acc[j][2] + e2b0[j]);
                        cs1[j] += lrelu(acc[j][3] + e2b1[j]);
                    }
                }
            }
            // butterfly over the 8 row-lanes (same qc)
            #pragma unroll
            for (int j = 0; j < 3; j++) {
                #pragma unroll
                for (int d = 4; d < 32; d <<= 1) {
                    cs0[j] += __shfl_xor_sync(0xFFFFFFFFu, cs0[j], d);
                    cs1[j] += __shfl_xor_sync(0xFFFFFFFFu, cs1[j], d);
                }
            }
            if (lane < 4) {
                float* gp = g_agg + bi * 192;
                #pragma unroll
                for (int j = 0; j < 3; j++) {
                    gp[n2[j] + 2 * lane]     = cs0[j];
                    gp[n2[j] + 2 * lane + 1] = cs1[j];
                }
            }
        }
        __syncthreads();   // all warps done before next bi overwrites h1/h2
    }
}

// ---------------- Node kernel: one CTA per 32 rows (unchanged) ----------------
#define O2_Y 0         // 32 * 200 = 6400 (195 used)
#define O2_H 6400      // 32 * 260 = 8320
#define O2_W 14720     // up to 65*256 = 16640
#define SMEM2_FL 31360
#define SMEM2_BYTES (SMEM2_FL * 4)

__global__ void __launch_bounds__(256, 1)
node_kernel(const float* __restrict__ x,
            const float* __restrict__ w1, const float* __restrict__ b1,
            const float* __restrict__ w2, const float* __restrict__ b2,
            const float* __restrict__ w3, const float* __restrict__ b3,
            float* __restrict__ out)
{
    extern __shared__ float s[];
    const int tid = threadIdx.x;
    const int row0 = blockIdx.x * 32;

    for (int idx = tid; idx < 32 * 192; idx += 256) {
        int r = idx / 192, c = idx - r * 192;
        s[O2_Y + r * 200 + c] = g_agg[(row0 + r) * 192 + c];
    }
    for (int idx = tid; idx < 96; idx += 256) {
        int r = idx / 3, c = idx - r * 3;
        s[O2_Y + r * 200 + 192 + c] = x[(row0 + r) * 3 + c];
    }

    const int cg = tid % 64, rg = tid / 64;
    const int c0 = cg * 4, r0 = rg * 8;

    float acc[8][4];
    #pragma unroll
    for (int m = 0; m < 8; m++)
        { acc[m][0]=0.f; acc[m][1]=0.f; acc[m][2]=0.f; acc[m][3]=0.f; }
    for (int kc = 0; kc < 3; kc++) {
        __syncthreads();
        {
            float4* d = (float4*)(s + O2_W);
            const float4* g = (const float4*)(w1 + kc * 65 * 256);
            for (int i = tid; i < (65 * 256) / 4; i += 256) d[i] = g[i];
        }
        __syncthreads();
        const int kbase = kc * 65;
        for (int k = 0; k < 65; k++) {
            float4 w = *(const float4*)(s + O2_W + k * 256 + c0);
            #pragma unroll
            for (int m = 0; m < 8; m++) {
                float h = s[O2_Y + (r0 + m) * 200 + kbase + k];
                acc[m][0] += h * w.x; acc[m][1] += h * w.y;
                acc[m][2] += h * w.z; acc[m][3] += h * w.w;
            }
        }
    }
    __syncthreads();
    {
        float4 bb = *(const float4*)(b1 + c0);
        #pragma unroll
        for (int m = 0; m < 8; m++) {
            float4 o;
            o.x = lrelu(acc[m][0] + bb.x);
            o.y = lrelu(acc[m][1] + bb.y);
            o.z = lrelu(acc[m][2] + bb.z);
            o.w = lrelu(acc[m][3] + bb.w);
            *(float4*)(s + O2_H + (r0 + m) * 260 + c0) = o;
        }
    }

    float acc2[8][4];
    #pragma unroll
    for (int m = 0; m < 8; m++)
        { acc2[m][0]=0.f; acc2[m][1]=0.f; acc2[m][2]=0.f; acc2[m][3]=0.f; }
    for (int kc = 0; kc < 4; kc++) {
        __syncthreads();
        {
            float4* d = (float4*)(s + O2_W);
            const float4* g = (const float4*)(w2 + kc * 64 * 256);
            for (int i = tid; i < (64 * 256) / 4; i += 256) d[i] = g[i];
        }
        __syncthreads();
        const int kbase = kc * 64;
        for (int k = 0; k < 64; k++) {
            float4 w = *(const float4*)(s + O2_W + k * 256 + c0);
            #pragma unroll
            for (int m = 0; m < 8; m++) {
                float h = s[O2_H + (r0 + m) * 260 + kbase + k];
                acc2[m][0] += h * w.x; acc2[m][1] += h * w.y;
                acc2[m][2] += h * w.z; acc2[m][3] += h * w.w;
            }
        }
    }
    __syncthreads();
    {
        float4 bb = *(const float4*)(b2 + c0);
        #pragma unroll
        for (int m = 0; m < 8; m++) {
            float4 o;
            o.x = lrelu(acc2[m][0] + bb.x);
            o.y = lrelu(acc2[m][1] + bb.y);
            o.z = lrelu(acc2[m][2] + bb.z);
            o.w = lrelu(acc2[m][3] + bb.w);
            *(float4*)(s + O2_H + (r0 + m) * 260 + c0) = o;
        }
    }
    __syncthreads();

    for (int idx = tid; idx < 768; idx += 256) s[O2_W + idx] = w3[idx];
    __syncthreads();
    if (tid < 96) {
        int r = tid / 3, o = tid - r * 3;
        float a = b3[o];
        for (int k = 0; k < 256; k++)
            a += s[O2_H + r * 260 + k] * s[O2_W + k * 3 + o];
        out[(row0 + r) * 3 + o] = a;
    }
}

extern "C" void kernel_launch(void* const* d_in, const int* in_sizes, int n_in,
                              void* d_out, int out_size)
{
    const float* x    = (const float*)d_in[0];
    const float* few1 = (const float*)d_in[1];
    const float* feb1 = (const float*)d_in[2];
    const float* few2 = (const float*)d_in[3];
    const float* feb2 = (const float*)d_in[4];
    const float* few3 = (const float*)d_in[5];
    const float* feb3 = (const float*)d_in[6];
    const float* fnw1 = (const float*)d_in[7];
    const float* fnb1 = (const float*)d_in[8];
    const float* fnw2 = (const float*)d_in[9];
    const float* fnb2 = (const float*)d_in[10];
    const float* fnw3 = (const float*)d_in[11];
    const float* fnb3 = (const float*)d_in[12];
    float* out = (float*)d_out;

    cudaFuncSetAttribute(edge_kernel, cudaFuncAttributeMaxDynamicSharedMemorySize, SMEM1_BYTES);
    cudaFuncSetAttribute(node_kernel, cudaFuncAttributeMaxDynamicSharedMemorySize, SMEM2_BYTES);

    edge_kernel<<<148, 256, SMEM1_BYTES>>>(x, few1, feb1, few2, feb2, few3, feb3);
    node_kernel<<<300, 256, SMEM2_BYTES>>>(x, fnw1, fnb1, fnw2, fnb2, fnw3, fnb3, out);
}

// round 8
// speedup vs baseline: 6.5468x; 1.1032x over previous
#include <cuda_runtime.h>
#include <cuda_fp16.h>
#include <cstdint>

#define ALPHA 0.2f

// Aggregated edge features scratch: [128*75, 192] = 7.37 MB (static, allowed)
static __device__ float g_agg[9600 * 192];

__device__ __forceinline__ float lrelu(float v) { return v > 0.0f ? v : ALPHA * v; }

// ---- packed fp32 helpers ----
#define FFMA2(acc, a, b) \
    asm("fma.rn.f32x2 %0, %1, %2, %0;" : "+l"(acc) : "l"(a), "l"(b))
__device__ __forceinline__ float2 unpack2(unsigned long long v) {
    float2 r;
    asm("mov.b64 {%0, %1}, %2;" : "=f"(r.x), "=f"(r.y) : "l"(v));
    return r;
}
__device__ __forceinline__ unsigned long long pack2(float lo, float hi) {
    unsigned long long r;
    asm("mov.b64 %0, {%1, %2};" : "=l"(r) : "f"(lo), "f"(hi));
    return r;
}
// pack two f32 -> f16x2 word: halves[0] = lo, halves[1] = hi
__device__ __forceinline__ uint32_t cvt_f16x2(float hi, float lo) {
    uint32_t d;
    asm("cvt.rn.f16x2.f32 %0, %1, %2;" : "=r"(d) : "f"(hi), "f"(lo));
    return d;
}
__device__ __forceinline__ uint32_t smem_u32(const void* p) {
    uint32_t a;
    asm("{ .reg .u64 t; cvta.to.shared.u64 t, %1; cvt.u32.u64 %0, t; }"
        : "=r"(a) : "l"(p));
    return a;
}

// ---- warp-level tensor core (sm_80+ path; valid on plain sm_103) ----
#define LDSM_X4(a0, a1, a2, a3, addr) \
    asm volatile("ldmatrix.sync.aligned.m8n8.x4.shared.b16 {%0,%1,%2,%3}, [%4];" \
                 : "=r"(a0), "=r"(a1), "=r"(a2), "=r"(a3) : "r"(addr))
#define LDSM_X2T(b0, b1, addr) \
    asm volatile("ldmatrix.sync.aligned.m8n8.x2.trans.shared.b16 {%0,%1}, [%2];" \
                 : "=r"(b0), "=r"(b1) : "r"(addr))
#define MMA16816(c, a0, a1, a2, a3, b0, b1) \
    asm volatile("mma.sync.aligned.m16n8k16.row.col.f32.f16.f16.f32 " \
                 "{%0,%1,%2,%3}, {%4,%5,%6,%7}, {%8,%9}, {%0,%1,%2,%3};" \
                 : "+f"((c)[0]), "+f"((c)[1]), "+f"((c)[2]), "+f"((c)[3]) \
                 : "r"(a0), "r"(a1), "r"(a2), "r"(a3), "r"(b0), "r"(b1))

// ================= EDGE KERNEL (unchanged from R7 win) =================
#define BW2 0        // W2 fp16 [96 k][168 n-stride]  (160 used)  = 32256 B
#define BW3 32256    // W3 fp16 [160 k][200 n-stride] (192 used)  = 64000 B
#define BH1 96256    // h1 fp16 [80 m][104 k-stride]  (96 used)   = 16640 B
#define BH2 112896   // h2 fp16 [80 m][168 k-stride]  (160 used)  = 26880 B
#define OF_W1 34944  // 672
#define OF_B2 35616  // 160
#define OF_B3 35776  // 192
#define OF_UI 35968  // 96
#define OF_XJ 36064  // 228
#define OF_D  36292  // 76
#define SMEM1_FL 36368
#define SMEM1_BYTES (SMEM1_FL * 4)
#define H1B32 (BH1 / 4)
#define H2B32 (BH2 / 4)

__global__ void __launch_bounds__(256, 1)
edge_kernel(const float* __restrict__ x,
            const float* __restrict__ w1, const float* __restrict__ b1,
            const float* __restrict__ w2, const float* __restrict__ b2,
            const float* __restrict__ w3, const float* __restrict__ b3)
{
    extern __shared__ float s[];
    uint32_t* s32 = (uint32_t*)s;
    __half* sh = (__half*)s;
    const int tid = threadIdx.x;
    const int wid = tid >> 5;
    const int lane = tid & 31;
    const uint32_t sbase = smem_u32(s);

    for (int i = tid; i < 672; i += 256) s[OF_W1 + i] = w1[i];
    for (int i = tid; i < 160; i += 256) s[OF_B2 + i] = b2[i];
    for (int i = tid; i < 192; i += 256) s[OF_B3 + i] = b3[i];
    for (int idx = tid; idx < 96 * 160; idx += 256) {
        int k = idx / 160, n = idx - k * 160;
        sh[k * 168 + n] = __float2half(w2[idx]);
    }
    for (int idx = tid; idx < 160 * 192; idx += 256) {
        int k = idx / 192, n = idx - k * 192;
        sh[BW3 / 2 + k * 200 + n] = __float2half(w3[idx]);
    }
    for (int idx = tid; idx < 5 * 52; idx += 256)
        s32[H1B32 + (75 + idx / 52) * 52 + (idx % 52)] = 0u;
    __syncthreads();

    const int nt1 = (wid < 4) ? 3 : 2;
    int n1[3], n2[3];
    #pragma unroll
    for (int j = 0; j < 3; j++) { n1[j] = 8 * wid + 64 * j; n2[j] = 8 * wid + 64 * j; }
    const int lA = lane & 15, gA = lane >> 4;
    const int lB = lane & 15;
    const int qr = lane >> 2, qc = lane & 3;
    const uint32_t a1base = sbase + BH1 + (uint32_t)(lA * 104 + gA * 8) * 2;
    const uint32_t a2base = sbase + BH2 + (uint32_t)(lA * 168 + gA * 8) * 2;
    const uint32_t b2base = sbase + BW2 + (uint32_t)(lB * 168) * 2;
    const uint32_t b3base = sbase + BW3 + (uint32_t)(lB * 200) * 2;
    float e1b0[3], e1b1[3], e2b0[3], e2b1[3];
    #pragma unroll
    for (int j = 0; j < 3; j++) {
        if (j < nt1) {
            e1b0[j] = s[OF_B2 + n1[j] + 2 * qc];
            e1b1[j] = s[OF_B2 + n1[j] + 2 * qc + 1];
        } else { e1b0[j] = 0.f; e1b1[j] = 0.f; }
        e2b0[j] = s[OF_B3 + n2[j] + 2 * qc];
        e2b1[j] = s[OF_B3 + n2[j] + 2 * qc + 1];
    }

    for (int bi = blockIdx.x; bi < 9600; bi += gridDim.x) {
        const int b = bi / 75, i = bi % 75;
        const float* xb = x + b * 75 * 3;
        const float xi0 = xb[i * 3 + 0], xi1 = xb[i * 3 + 1], xi2 = xb[i * 3 + 2];

        if (tid < 75) {
            float a0 = xb[tid * 3 + 0], a1 = xb[tid * 3 + 1], a2 = xb[tid * 3 + 2];
            s[OF_XJ + 3 * tid + 0] = a0;
            s[OF_XJ + 3 * tid + 1] = a1;
            s[OF_XJ + 3 * tid + 2] = a2;
            float d0 = (a0 - xi0) + 1e-12f;
            float d1 = (a1 - xi1) + 1e-12f;
            float d2 = (a2 - xi2) + 1e-12f;
            s[OF_D + tid] = sqrtf(d0 * d0 + d1 * d1 + d2 * d2);
        }
        if (tid >= 160) {
            int c = tid - 160;
            s[OF_UI + c] = b1[c] + xi0 * s[OF_W1 + c]
                                 + xi1 * s[OF_W1 + 96 + c]
                                 + xi2 * s[OF_W1 + 192 + c];
        }
        __syncthreads();

        for (int idx = tid; idx < 75 * 48; idx += 256) {
            int r = idx / 48, w = idx - r * 48;
            float xj0 = s[OF_XJ + 3 * r + 0];
            float xj1 = s[OF_XJ + 3 * r + 1];
            float xj2 = s[OF_XJ + 3 * r + 2];
            float dj  = s[OF_D + r];
            unsigned long long v = *(const unsigned long long*)(s + OF_UI + 2 * w);
            FFMA2(v, pack2(xj0, xj0), *(const unsigned long long*)(s + OF_W1 + 288 + 2 * w));
            FFMA2(v, pack2(xj1, xj1), *(const unsigned long long*)(s + OF_W1 + 384 + 2 * w));
            FFMA2(v, pack2(xj2, xj2), *(const unsigned long long*)(s + OF_W1 + 480 + 2 * w));
            FFMA2(v, pack2(dj, dj),   *(const unsigned long long*)(s + OF_W1 + 576 + 2 * w));
            float2 vf = unpack2(v);
            s32[H1B32 + r * 52 + w] = cvt_f16x2(lrelu(vf.y), lrelu(vf.x));
        }
        __syncthreads();

        {
            float acc[5][3][4];
            #pragma unroll
            for (int m = 0; m < 5; m++)
                #pragma unroll
                for (int j = 0; j < 3; j++)
                    { acc[m][j][0]=0.f; acc[m][j][1]=0.f; acc[m][j][2]=0.f; acc[m][j][3]=0.f; }
            #pragma unroll
            for (int k = 0; k < 6; k++) {
                uint32_t bf[3][2];
                #pragma unroll
                for (int j = 0; j < 3; j++)
                    if (j < nt1) { LDSM_X2T(bf[j][0], bf[j][1], b2base + k * 5376 + n1[j] * 2); }
                #pragma unroll
                for (int m = 0; m < 5; m++) {
                    uint32_t a0, a1, a2, a3;
                    LDSM_X4(a0, a1, a2, a3, a1base + m * 3328 + k * 32);
                    #pragma unroll
                    for (int j = 0; j < 3; j++)
                        if (j < nt1) MMA16816(acc[m][j], a0, a1, a2, a3, bf[j][0], bf[j][1]);
                }
            }
            #pragma unroll
            for (int m = 0; m < 5; m++) {
                int r1 = m * 16 + qr, r2 = r1 + 8;
                #pragma unroll
                for (int j = 0; j < 3; j++)
                    if (j < nt1) {
                        uint32_t u = n1[j] / 2 + qc;
                        s32[H2B32 + r1 * 84 + u] =
                            cvt_f16x2(lrelu(acc[m][j][1] + e1b1[j]),
                                      lrelu(acc[m][j][0] + e1b0[j]));
                        s32[H2B32 + r2 * 84 + u] =
                            cvt_f16x2(lrelu(acc[m][j][3] + e1b1[j]),
                                      lrelu(acc[m][j][2] + e1b0[j]));
                    }
            }
        }
        __syncthreads();

        {
            float cs0[3] = {0.f, 0.f, 0.f}, cs1[3] = {0.f, 0.f, 0.f};
            #pragma unroll
            for (int m = 0; m < 5; m++) {
                float acc[3][4];
                #pragma unroll
                for (int j = 0; j < 3; j++)
                    { acc[j][0]=0.f; acc[j][1]=0.f; acc[j][2]=0.f; acc[j][3]=0.f; }
                #pragma unroll
                for (int k = 0; k < 10; k++) {
                    uint32_t a0, a1, a2, a3;
                    LDSM_X4(a0, a1, a2, a3, a2base + m * 5376 + k * 32);
                    #pragma unroll
                    for (int j = 0; j < 3; j++) {
                        uint32_t b0, b1;
                        LDSM_X2T(b0, b1, b3base + k * 6400 + n2[j] * 2);
                        MMA16816(acc[j], a0, a1, a2, a3, b0, b1);
                    }
                }
                bool ok2 = (m * 16 + 8 + qr) < 75;
                #pragma unroll
                for (int j = 0; j < 3; j++) {
                    cs0[j] += lrelu(acc[j][0] + e2b0[j]);
                    cs1[j] += lrelu(acc[j][1] + e2b1[j]);
                    if (ok2) {
                        cs0[j] += lrelu(acc[j][2] + e2b0[j]);
                        cs1[j] += lrelu(acc[j][3] + e2b1[j]);
                    }
                }
            }
            #pragma unroll
            for (int j = 0; j < 3; j++) {
                #pragma unroll
                for (int d = 4; d < 32; d <<= 1) {
                    cs0[j] += __shfl_xor_sync(0xFFFFFFFFu, cs0[j], d);
                    cs1[j] += __shfl_xor_sync(0xFFFFFFFFu, cs1[j], d);
                }
            }
            if (lane < 4) {
                float* gp = g_agg + bi * 192;
                #pragma unroll
                for (int j = 0; j < 3; j++) {
                    gp[n2[j] + 2 * lane]     = cs0[j];
                    gp[n2[j] + 2 * lane + 1] = cs1[j];
                }
            }
        }
        __syncthreads();
    }
}

// ================= NODE KERNEL — HMMA rewrite =================
// 64 rows/CTA, grid 150. SMEM byte layout:
//   BW  = 0       weights region (max: W2 256 x 264 fp16 = 135168 B)
//   BH1n= 135168  h1 tile 64 x 264 fp16 = 33792 B
//   BYn = 168960  y tile (64 x 216 fp16 = 27648) / h2 tile (64 x 264 = 33792)
//   f32 region at 202752 B: b1(256), b2(256), w3(768), b3(4)
#define BWN   0
#define BH1N  135168
#define BYN   168960
#define OFN_B1 50688
#define OFN_B2 50944
#define OFN_W3 51200
#define OFN_B3 51968
#define SMEM2_FL 51972
#define SMEM2_BYTES (SMEM2_FL * 4)
#define H1NU (BH1N / 4)
#define YNU  (BYN / 4)

__global__ void __launch_bounds__(256, 1)
node_kernel(const float* __restrict__ x,
            const float* __restrict__ w1, const float* __restrict__ b1,
            const float* __restrict__ w2, const float* __restrict__ b2,
            const float* __restrict__ w3, const float* __restrict__ b3,
            float* __restrict__ out)
{
    extern __shared__ float s[];
    uint32_t* s32 = (uint32_t*)s;
    __half* sh = (__half*)s;
    const int tid = threadIdx.x;
    const int wid = tid >> 5;
    const int lane = tid & 31;
    const uint32_t sbase = smem_u32(s);
    const int row0 = blockIdx.x * 64;

    const int lA = lane & 15, gA = lane >> 4;
    const int lB = lane & 15;
    const int qr = lane >> 2, qc = lane & 3;
    const int n0 = 32 * wid;                          // warp's 32-col slab
    const uint32_t aYbase  = sbase + BYN  + (uint32_t)(lA * 216 + gA * 8) * 2;
    const uint32_t aH1base = sbase + BH1N + (uint32_t)(lA * 264 + gA * 8) * 2;
    const uint32_t bWbase  = sbase + BWN  + (uint32_t)(lB * 264) * 2;

    // ---- Stage 0: biases/w3 + y tile + W1 fp16 ----
    for (int i = tid; i < 256; i += 256) s[OFN_B1 + i] = b1[i];
    for (int i = tid; i < 256; i += 256) s[OFN_B2 + i] = b2[i];
    for (int i = tid; i < 768; i += 256) s[OFN_W3 + i] = w3[i];
    if (tid < 3) s[OFN_B3 + tid] = b3[tid];

    // y[64][216]: [agg(192) | x(3) | zeros(213..215 incl. pad)]
    for (int idx = tid; idx < 64 * 108; idx += 256) {
        int r = idx / 108, u = idx - r * 108;
        int gr = row0 + r;
        uint32_t v;
        if (u < 96) {
            const float* gp = g_agg + (size_t)gr * 192 + 2 * u;
            v = cvt_f16x2(gp[1], gp[0]);
        } else if (u == 96) {
            v = cvt_f16x2(x[gr * 3 + 1], x[gr * 3 + 0]);
        } else if (u == 97) {
            v = cvt_f16x2(0.f, x[gr * 3 + 2]);
        } else v = 0u;
        s32[YNU + r * 108 + u] = v;
    }
    // W1 fp16 [208 k][264 stride] (195 valid rows, 256 valid cols)
    for (int idx = tid; idx < 208 * 132; idx += 256) {
        int k = idx / 132, u = idx - k * 132;
        uint32_t v = 0u;
        if (k < 195 && u < 128) {
            const float* gp = w1 + (size_t)k * 256 + 2 * u;
            v = cvt_f16x2(gp[1], gp[0]);
        }
        s32[k * 132 + u] = v;
    }
    __syncthreads();

    // ---- Phase 1: h1[64][256] = lrelu(y @ W1 + b1), K = 208 (13 chunks) ----
    {
        float acc[4][4][4];
        #pragma unroll
        for (int m = 0; m < 4; m++)
            #pragma unroll
            for (int j = 0; j < 4; j++)
                { acc[m][j][0]=0.f; acc[m][j][1]=0.f; acc[m][j][2]=0.f; acc[m][j][3]=0.f; }
        #pragma unroll
        for (int kc = 0; kc < 13; kc++) {
            uint32_t bf[4][2];
            #pragma unroll
            for (int j = 0; j < 4; j++)
                LDSM_X2T(bf[j][0], bf[j][1], bWbase + kc * 8448 + (n0 + 8 * j) * 2);
            #pragma unroll
            for (int m = 0; m < 4; m++) {
                uint32_t a0, a1, a2, a3;
                LDSM_X4(a0, a1, a2, a3, aYbase + m * 6912 + kc * 32);
                #pragma unroll
                for (int j = 0; j < 4; j++)
                    MMA16816(acc[m][j], a0, a1, a2, a3, bf[j][0], bf[j][1]);
            }
        }
        #pragma unroll
        for (int m = 0; m < 4; m++) {
            int r1 = m * 16 + qr, r2 = r1 + 8;
            #pragma unroll
            for (int j = 0; j < 4; j++) {
                float bb0 = s[OFN_B1 + n0 + 8 * j + 2 * qc];
                float bb1 = s[OFN_B1 + n0 + 8 * j + 2 * qc + 1];
                uint32_t u = n0 / 2 + 4 * j + qc;
                s32[H1NU + r1 * 132 + u] =
                    cvt_f16x2(lrelu(acc[m][j][1] + bb1), lrelu(acc[m][j][0] + bb0));
                s32[H1NU + r2 * 132 + u] =
                    cvt_f16x2(lrelu(acc[m][j][3] + bb1), lrelu(acc[m][j][2] + bb0));
            }
        }
    }
    __syncthreads();

    // ---- Stage: overwrite weights region with W2 fp16 [256][264] ----
    for (int idx = tid; idx < 256 * 132; idx += 256) {
        int k = idx / 132, u = idx - k * 132;
        uint32_t v = 0u;
        if (u < 128) {
            const float* gp = w2 + (size_t)k * 256 + 2 * u;
            v = cvt_f16x2(gp[1], gp[0]);
        }
        s32[k * 132 + u] = v;
    }
    __syncthreads();

    // ---- Phase 2: h2[64][256] = lrelu(h1 @ W2 + b2), K = 256 (16 chunks) ----
    // h2 written to the y slot (y is dead).
    {
        float acc[4][4][4];
        #pragma unroll
        for (int m = 0; m < 4; m++)
            #pragma unroll
            for (int j = 0; j < 4; j++)
                { acc[m][j][0]=0.f; acc[m][j][1]=0.f; acc[m][j][2]=0.f; acc[m][j][3]=0.f; }
        #pragma unroll
        for (int kc = 0; kc < 16; kc++) {
            uint32_t bf[4][2];
            #pragma unroll
            for (int j = 0; j < 4; j++)
                LDSM_X2T(bf[j][0], bf[j][1], bWbase + kc * 8448 + (n0 + 8 * j) * 2);
            #pragma unroll
            for (int m = 0; m < 4; m++) {
                uint32_t a0, a1, a2, a3;
                LDSM_X4(a0, a1, a2, a3, aH1base + m * 8448 + kc * 32);
                #pragma unroll
                for (int j = 0; j < 4; j++)
                    MMA16816(acc[m][j], a0, a1, a2, a3, bf[j][0], bf[j][1]);
            }
        }
        #pragma unroll
        for (int m = 0; m < 4; m++) {
            int r1 = m * 16 + qr, r2 = r1 + 8;
            #pragma unroll
            for (int j = 0; j < 4; j++) {
                float bb0 = s[OFN_B2 + n0 + 8 * j + 2 * qc];
                float bb1 = s[OFN_B2 + n0 + 8 * j + 2 * qc + 1];
                uint32_t u = n0 / 2 + 4 * j + qc;
                s32[YNU + r1 * 132 + u] =
                    cvt_f16x2(lrelu(acc[m][j][1] + bb1), lrelu(acc[m][j][0] + bb0));
                s32[YNU + r2 * 132 + u] =
                    cvt_f16x2(lrelu(acc[m][j][3] + bb1), lrelu(acc[m][j][2] + bb0));
            }
        }
    }
    __syncthreads();

    // ---- Phase 3: out[64][3] = h2 @ W3 + b3 (fp32 scalar) ----
    if (tid < 192) {
        int r = tid / 3, o = tid - r * 3;
        const __half* hr = sh + BYN / 2 + r * 264;
        float a = s[OFN_B3 + o];
        #pragma unroll 8
        for (int k = 0; k < 256; k++)
            a += __half2float(hr[k]) * s[OFN_W3 + k * 3 + o];
        out[(row0 + r) * 3 + o] = a;
    }
}

extern "C" void kernel_launch(void* const* d_in, const int* in_sizes, int n_in,
                              void* d_out, int out_size)
{
    const float* x    = (const float*)d_in[0];
    const float* few1 = (const float*)d_in[1];
    const float* feb1 = (const float*)d_in[2];
    const float* few2 = (const float*)d_in[3];
    const float* feb2 = (const float*)d_in[4];
    const float* few3 = (const float*)d_in[5];
    const float* feb3 = (const float*)d_in[6];
    const float* fnw1 = (const float*)d_in[7];
    const float* fnb1 = (const float*)d_in[8];
    const float* fnw2 = (const float*)d_in[9];
    const float* fnb2 = (const float*)d_in[10];
    const float* fnw3 = (const float*)d_in[11];
    const float* fnb3 = (const float*)d_in[12];
    float* out = (float*)d_out;

    cudaFuncSetAttribute(edge_kernel, cudaFuncAttributeMaxDynamicSharedMemorySize, SMEM1_BYTES);
    cudaFuncSetAttribute(node_kernel, cudaFuncAttributeMaxDynamicSharedMemorySize, SMEM2_BYTES);

    edge_kernel<<<148, 256, SMEM1_BYTES>>>(x, few1, feb1, few2, feb2, few3, feb3);
    node_kernel<<<150, 256, SMEM2_BYTES>>>(x, fnw1, fnb1, fnw2, fnb2, fnw3, fnb3, out);
}

// round 9
// speedup vs baseline: 6.7360x; 1.0289x over previous
#include <cuda_runtime.h>
#include <cuda_fp16.h>
#include <cstdint>

#define ALPHA 0.2f

// Aggregated edge features scratch: [128*75, 192] = 7.37 MB (static, allowed)
static __device__ float g_agg[9600 * 192];
// Pre-converted fp16 node weights, already in node-SMEM layout (u32 = f16x2, stride 132)
static __device__ uint4 g_w1h[208 * 132 / 4];   // 195x256 valid, zero-padded
static __device__ uint4 g_w2h[256 * 132 / 4];

__device__ __forceinline__ float lrelu(float v) { return v > 0.0f ? v : ALPHA * v; }

// ---- packed fp32 helpers ----
#define FFMA2(acc, a, b) \
    asm("fma.rn.f32x2 %0, %1, %2, %0;" : "+l"(acc) : "l"(a), "l"(b))
__device__ __forceinline__ float2 unpack2(unsigned long long v) {
    float2 r;
    asm("mov.b64 {%0, %1}, %2;" : "=f"(r.x), "=f"(r.y) : "l"(v));
    return r;
}
__device__ __forceinline__ unsigned long long pack2(float lo, float hi) {
    unsigned long long r;
    asm("mov.b64 %0, {%1, %2};" : "=l"(r) : "f"(lo), "f"(hi));
    return r;
}
// pack two f32 -> f16x2 word: halves[0] = lo, halves[1] = hi
__device__ __forceinline__ uint32_t cvt_f16x2(float hi, float lo) {
    uint32_t d;
    asm("cvt.rn.f16x2.f32 %0, %1, %2;" : "=r"(d) : "f"(hi), "f"(lo));
    return d;
}
__device__ __forceinline__ uint32_t smem_u32(const void* p) {
    uint32_t a;
    asm("{ .reg .u64 t; cvta.to.shared.u64 t, %1; cvt.u32.u64 %0, t; }"
        : "=r"(a) : "l"(p));
    return a;
}

// ---- warp-level tensor core (sm_80+ path; valid on plain sm_103) ----
#define LDSM_X4(a0, a1, a2, a3, addr) \
    asm volatile("ldmatrix.sync.aligned.m8n8.x4.shared.b16 {%0,%1,%2,%3}, [%4];" \
                 : "=r"(a0), "=r"(a1), "=r"(a2), "=r"(a3) : "r"(addr))
#define LDSM_X2T(b0, b1, addr) \
    asm volatile("ldmatrix.sync.aligned.m8n8.x2.trans.shared.b16 {%0,%1}, [%2];" \
                 : "=r"(b0), "=r"(b1) : "r"(addr))
#define MMA16816(c, a0, a1, a2, a3, b0, b1) \
    asm volatile("mma.sync.aligned.m16n8k16.row.col.f32.f16.f16.f32 " \
                 "{%0,%1,%2,%3}, {%4,%5,%6,%7}, {%8,%9}, {%0,%1,%2,%3};" \
                 : "+f"((c)[0]), "+f"((c)[1]), "+f"((c)[2]), "+f"((c)[3]) \
                 : "r"(a0), "r"(a1), "r"(a2), "r"(a3), "r"(b0), "r"(b1))

// ================= PREP KERNEL: fn weights -> fp16 layout =================
__global__ void __launch_bounds__(256)
prep_kernel(const float* __restrict__ w1, const float* __restrict__ w2)
{
    int i = blockIdx.x * 256 + threadIdx.x;
    if (i < 208 * 132) {
        int k = i / 132, u = i - k * 132;
        uint32_t v = 0u;
        if (k < 195 && u < 128)
            v = cvt_f16x2(w1[(size_t)k * 256 + 2 * u + 1], w1[(size_t)k * 256 + 2 * u]);
        ((uint32_t*)g_w1h)[i] = v;
    }
    if (i < 256 * 132) {
        int k = i / 132, u = i - k * 132;
        uint32_t v = 0u;
        if (u < 128)
            v = cvt_f16x2(w2[(size_t)k * 256 + 2 * u + 1], w2[(size_t)k * 256 + 2 * u]);
        ((uint32_t*)g_w2h)[i] = v;
    }
}

// ================= EDGE KERNEL =================
#define BW2 0        // W2 fp16 [96 k][168 n-stride]  (160 used)  = 32256 B
#define BW3 32256    // W3 fp16 [160 k][200 n-stride] (192 used)  = 64000 B
#define BH1 96256    // h1 fp16 [80 m][104 k-stride]  (96 used)   = 16640 B
#define BH2 112896   // h2 fp16 [80 m][168 k-stride]  (160 used)  = 26880 B
#define OF_W1 34944  // 672
#define OF_B2 35616  // 160
#define OF_B3 35776  // 192
#define OF_UI 35968  // 96
#define OF_XJ 36064  // 228
#define OF_D  36292  // 76
#define SMEM1_FL 36368
#define SMEM1_BYTES (SMEM1_FL * 4)
#define H1B32 (BH1 / 4)
#define H2B32 (BH2 / 4)

__global__ void __launch_bounds__(256, 1)
edge_kernel(const float* __restrict__ x,
            const float* __restrict__ w1, const float* __restrict__ b1,
            const float* __restrict__ w2, const float* __restrict__ b2,
            const float* __restrict__ w3, const float* __restrict__ b3)
{
    extern __shared__ float s[];
    uint32_t* s32 = (uint32_t*)s;
    __half* sh = (__half*)s;
    const int tid = threadIdx.x;
    const int wid = tid >> 5;
    const int lane = tid & 31;
    const uint32_t sbase = smem_u32(s);

    for (int i = tid; i < 672; i += 256) s[OF_W1 + i] = w1[i];
    for (int i = tid; i < 160; i += 256) s[OF_B2 + i] = b2[i];
    for (int i = tid; i < 192; i += 256) s[OF_B3 + i] = b3[i];
    for (int idx = tid; idx < 96 * 160; idx += 256) {
        int k = idx / 160, n = idx - k * 160;
        sh[k * 168 + n] = __float2half(w2[idx]);
    }
    for (int idx = tid; idx < 160 * 192; idx += 256) {
        int k = idx / 192, n = idx - k * 192;
        sh[BW3 / 2 + k * 200 + n] = __float2half(w3[idx]);
    }
    for (int idx = tid; idx < 5 * 52; idx += 256)
        s32[H1B32 + (75 + idx / 52) * 52 + (idx % 52)] = 0u;
    __syncthreads();

    const int nt1 = (wid < 4) ? 3 : 2;
    int n1[3], n2[3];
    #pragma unroll
    for (int j = 0; j < 3; j++) { n1[j] = 8 * wid + 64 * j; n2[j] = 8 * wid + 64 * j; }
    const int lA = lane & 15, gA = lane >> 4;
    const int lB = lane & 15;
    const int qr = lane >> 2, qc = lane & 3;
    const uint32_t a1base = sbase + BH1 + (uint32_t)(lA * 104 + gA * 8) * 2;
    const uint32_t a2base = sbase + BH2 + (uint32_t)(lA * 168 + gA * 8) * 2;
    const uint32_t b2base = sbase + BW2 + (uint32_t)(lB * 168) * 2;
    const uint32_t b3base = sbase + BW3 + (uint32_t)(lB * 200) * 2;
    float e1b0[3], e1b1[3], e2b0[3], e2b1[3];
    #pragma unroll
    for (int j = 0; j < 3; j++) {
        if (j < nt1) {
            e1b0[j] = s[OF_B2 + n1[j] + 2 * qc];
            e1b1[j] = s[OF_B2 + n1[j] + 2 * qc + 1];
        } else { e1b0[j] = 0.f; e1b1[j] = 0.f; }
        e2b0[j] = s[OF_B3 + n2[j] + 2 * qc];
        e2b1[j] = s[OF_B3 + n2[j] + 2 * qc + 1];
    }

    for (int bi = blockIdx.x; bi < 9600; bi += gridDim.x) {
        const int b = bi / 75, i = bi % 75;
        const float* xb = x + b * 75 * 3;
        const float xi0 = xb[i * 3 + 0], xi1 = xb[i * 3 + 1], xi2 = xb[i * 3 + 2];

        if (tid < 75) {
            float a0 = xb[tid * 3 + 0], a1 = xb[tid * 3 + 1], a2 = xb[tid * 3 + 2];
            s[OF_XJ + 3 * tid + 0] = a0;
            s[OF_XJ + 3 * tid + 1] = a1;
            s[OF_XJ + 3 * tid + 2] = a2;
            float d0 = (a0 - xi0) + 1e-12f;
            float d1 = (a1 - xi1) + 1e-12f;
            float d2 = (a2 - xi2) + 1e-12f;
            s[OF_D + tid] = sqrtf(d0 * d0 + d1 * d1 + d2 * d2);
        }
        if (tid >= 160) {
            int c = tid - 160;
            s[OF_UI + c] = b1[c] + xi0 * s[OF_W1 + c]
                                 + xi1 * s[OF_W1 + 96 + c]
                                 + xi2 * s[OF_W1 + 192 + c];
        }
        __syncthreads();

        for (int idx = tid; idx < 75 * 48; idx += 256) {
            int r = idx / 48, w = idx - r * 48;
            float xj0 = s[OF_XJ + 3 * r + 0];
            float xj1 = s[OF_XJ + 3 * r + 1];
            float xj2 = s[OF_XJ + 3 * r + 2];
            float dj  = s[OF_D + r];
            unsigned long long v = *(const unsigned long long*)(s + OF_UI + 2 * w);
            FFMA2(v, pack2(xj0, xj0), *(const unsigned long long*)(s + OF_W1 + 288 + 2 * w));
            FFMA2(v, pack2(xj1, xj1), *(const unsigned long long*)(s + OF_W1 + 384 + 2 * w));
            FFMA2(v, pack2(xj2, xj2), *(const unsigned long long*)(s + OF_W1 + 480 + 2 * w));
            FFMA2(v, pack2(dj, dj),   *(const unsigned long long*)(s + OF_W1 + 576 + 2 * w));
            float2 vf = unpack2(v);
            s32[H1B32 + r * 52 + w] = cvt_f16x2(lrelu(vf.y), lrelu(vf.x));
        }
        __syncthreads();

        // ---- MMA1: D1[80][160] = h1 @ W2 ; epi -> h2 fp16 ----
        {
            float acc[5][3][4];
            #pragma unroll
            for (int m = 0; m < 5; m++)
                #pragma unroll
                for (int j = 0; j < 3; j++)
                    { acc[m][j][0]=0.f; acc[m][j][1]=0.f; acc[m][j][2]=0.f; acc[m][j][3]=0.f; }
            #pragma unroll
            for (int k = 0; k < 6; k++) {
                uint32_t bf[3][2];
                #pragma unroll
                for (int j = 0; j < 3; j++)
                    if (j < nt1) { LDSM_X2T(bf[j][0], bf[j][1], b2base + k * 5376 + n1[j] * 2); }
                #pragma unroll
                for (int m = 0; m < 5; m++) {
                    uint32_t a0, a1, a2, a3;
                    LDSM_X4(a0, a1, a2, a3, a1base + m * 3328 + k * 32);
                    #pragma unroll
                    for (int j = 0; j < 3; j++)
                        if (j < nt1) MMA16816(acc[m][j], a0, a1, a2, a3, bf[j][0], bf[j][1]);
                }
            }
            #pragma unroll
            for (int m = 0; m < 5; m++) {
                int r1 = m * 16 + qr, r2 = r1 + 8;
                #pragma unroll
                for (int j = 0; j < 3; j++)
                    if (j < nt1) {
                        uint32_t u = n1[j] / 2 + qc;
                        s32[H2B32 + r1 * 84 + u] =
                            cvt_f16x2(lrelu(acc[m][j][1] + e1b1[j]),
                                      lrelu(acc[m][j][0] + e1b0[j]));
                        s32[H2B32 + r2 * 84 + u] =
                            cvt_f16x2(lrelu(acc[m][j][3] + e1b1[j]),
                                      lrelu(acc[m][j][2] + e1b0[j]));
                    }
            }
        }
        __syncthreads();

        // ---- MMA2 (k-outer, B-frags hoisted): D2[80][192] = h2 @ W3 ----
        {
            float acc[5][3][4];
            #pragma unroll
            for (int m = 0; m < 5; m++)
                #pragma unroll
                for (int j = 0; j < 3; j++)
                    { acc[m][j][0]=0.f; acc[m][j][1]=0.f; acc[m][j][2]=0.f; acc[m][j][3]=0.f; }
            #pragma unroll
            for (int k = 0; k < 10; k++) {
                uint32_t bf[3][2];
                #pragma unroll
                for (int j = 0; j < 3; j++)
                    LDSM_X2T(bf[j][0], bf[j][1], b3base + k * 6400 + n2[j] * 2);
                #pragma unroll
                for (int m = 0; m < 5; m++) {
                    uint32_t a0, a1, a2, a3;
                    LDSM_X4(a0, a1, a2, a3, a2base + m * 5376 + k * 32);
                    #pragma unroll
                    for (int j = 0; j < 3; j++)
                        MMA16816(acc[m][j], a0, a1, a2, a3, bf[j][0], bf[j][1]);
                }
            }
            float cs0[3] = {0.f, 0.f, 0.f}, cs1[3] = {0.f, 0.f, 0.f};
            #pragma unroll
            for (int m = 0; m < 5; m++) {
                bool ok2 = (m * 16 + 8 + qr) < 75;
                #pragma unroll
                for (int j = 0; j < 3; j++) {
                    cs0[j] += lrelu(acc[m][j][0] + e2b0[j]);
                    cs1[j] += lrelu(acc[m][j][1] + e2b1[j]);
                    if (ok2) {
                        cs0[j] += lrelu(acc[m][j][2] + e2b0[j]);
                        cs1[j] += lrelu(acc[m][j][3] + e2b1[j]);
                    }
                }
            }
            #pragma unroll
            for (int j = 0; j < 3; j++) {
                #pragma unroll
                for (int d = 4; d < 32; d <<= 1) {
                    cs0[j] += __shfl_xor_sync(0xFFFFFFFFu, cs0[j], d);
                    cs1[j] += __shfl_xor_sync(0xFFFFFFFFu, cs1[j], d);
                }
            }
            if (lane < 4) {
                float* gp = g_agg + bi * 192;
                #pragma unroll
                for (int j = 0; j < 3; j++) {
                    gp[n2[j] + 2 * lane]     = cs0[j];
                    gp[n2[j] + 2 * lane + 1] = cs1[j];
                }
            }
        }
        __syncthreads();
    }
}

// ================= NODE KERNEL — HMMA =================
#define BWN   0
#define BH1N  135168
#define BYN   168960
#define OFN_B1 50688
#define OFN_B2 50944
#define OFN_W3 51200
#define OFN_B3 51968
#define SMEM2_FL 51972
#define SMEM2_BYTES (SMEM2_FL * 4)
#define H1NU (BH1N / 4)
#define YNU  (BYN / 4)

__global__ void __launch_bounds__(256, 1)
node_kernel(const float* __restrict__ x,
            const float* __restrict__ b1,
            const float* __restrict__ b2,
            const float* __restrict__ w3, const float* __restrict__ b3,
            float* __restrict__ out)
{
    extern __shared__ float s[];
    uint32_t* s32 = (uint32_t*)s;
    __half* sh = (__half*)s;
    const int tid = threadIdx.x;
    const int wid = tid >> 5;
    const int lane = tid & 31;
    const uint32_t sbase = smem_u32(s);
    const int row0 = blockIdx.x * 64;

    const int lA = lane & 15, gA = lane >> 4;
    const int lB = lane & 15;
    const int qr = lane >> 2, qc = lane & 3;
    const int n0 = 32 * wid;
    const uint32_t aYbase  = sbase + BYN  + (uint32_t)(lA * 216 + gA * 8) * 2;
    const uint32_t aH1base = sbase + BH1N + (uint32_t)(lA * 264 + gA * 8) * 2;
    const uint32_t bWbase  = sbase + BWN  + (uint32_t)(lB * 264) * 2;

    // ---- Stage 0: biases/w3 + y tile + W1 fp16 (pure uint4 copy) ----
    for (int i = tid; i < 256; i += 256) s[OFN_B1 + i] = b1[i];
    for (int i = tid; i < 256; i += 256) s[OFN_B2 + i] = b2[i];
    for (int i = tid; i < 768; i += 256) s[OFN_W3 + i] = w3[i];
    if (tid < 3) s[OFN_B3 + tid] = b3[tid];

    for (int idx = tid; idx < 64 * 108; idx += 256) {
        int r = idx / 108, u = idx - r * 108;
        int gr = row0 + r;
        uint32_t v;
        if (u < 96) {
            const float* gp = g_agg + (size_t)gr * 192 + 2 * u;
            v = cvt_f16x2(gp[1], gp[0]);
        } else if (u == 96) {
            v = cvt_f16x2(x[gr * 3 + 1], x[gr * 3 + 0]);
        } else if (u == 97) {
            v = cvt_f16x2(0.f, x[gr * 3 + 2]);
        } else v = 0u;
        s32[YNU + r * 108 + u] = v;
    }
    {
        uint4* d = (uint4*)s32;
        for (int i = tid; i < 208 * 132 / 4; i += 256) d[i] = g_w1h[i];
    }
    __syncthreads();

    // ---- Phase 1: h1[64][256] = lrelu(y @ W1 + b1), K = 208 ----
    {
        float acc[4][4][4];
        #pragma unroll
        for (int m = 0; m < 4; m++)
            #pragma unroll
            for (int j = 0; j < 4; j++)
                { acc[m][j][0]=0.f; acc[m][j][1]=0.f; acc[m][j][2]=0.f; acc[m][j][3]=0.f; }
        #pragma unroll
        for (int kc = 0; kc < 13; kc++) {
            uint32_t bf[4][2];
            #pragma unroll
            for (int j = 0; j < 4; j++)
                LDSM_X2T(bf[j][0], bf[j][1], bWbase + kc * 8448 + (n0 + 8 * j) * 2);
            #pragma unroll
            for (int m = 0; m < 4; m++) {
                uint32_t a0, a1, a2, a3;
                LDSM_X4(a0, a1, a2, a3, aYbase + m * 6912 + kc * 32);
                #pragma unroll
                for (int j = 0; j < 4; j++)
                    MMA16816(acc[m][j], a0, a1, a2, a3, bf[j][0], bf[j][1]);
            }
        }
        #pragma unroll
        for (int m = 0; m < 4; m++) {
            int r1 = m * 16 + qr, r2 = r1 + 8;
            #pragma unroll
            for (int j = 0; j < 4; j++) {
                float bb0 = s[OFN_B1 + n0 + 8 * j + 2 * qc];
                float bb1 = s[OFN_B1 + n0 + 8 * j + 2 * qc + 1];
                uint32_t u = n0 / 2 + 4 * j + qc;
                s32[H1NU + r1 * 132 + u] =
                    cvt_f16x2(lrelu(acc[m][j][1] + bb1), lrelu(acc[m][j][0] + bb0));
                s32[H1NU + r2 * 132 + u] =
                    cvt_f16x2(lrelu(acc[m][j][3] + bb1), lrelu(acc[m][j][2] + bb0));
            }
        }
    }
    __syncthreads();

    // ---- Stage: W2 fp16 (pure uint4 copy) ----
    {
        uint4* d = (uint4*)s32;
        for (int i = tid; i < 256 * 132 / 4; i += 256) d[i] = g_w2h[i];
    }
    __syncthreads();

    // ---- Phase 2: h2[64][256] = lrelu(h1 @ W2 + b2), K = 256 ----
    {
        float acc[4][4][4];
        #pragma unroll
        for (int m = 0; m < 4; m++)
            #pragma unroll
            for (int j = 0; j < 4; j++)
                { acc[m][j][0]=0.f; acc[m][j][1]=0.f; acc[m][j][2]=0.f; acc[m][j][3]=0.f; }
        #pragma unroll
        for (int kc = 0; kc < 16; kc++) {
            uint32_t bf[4][2];
            #pragma unroll
            for (int j = 0; j < 4; j++)
                LDSM_X2T(bf[j][0], bf[j][1], bWbase + kc * 8448 + (n0 + 8 * j) * 2);
            #pragma unroll
            for (int m = 0; m < 4; m++) {
                uint32_t a0, a1, a2, a3;
                LDSM_X4(a0, a1, a2, a3, aH1base + m * 8448 + kc * 32);
                #pragma unroll
                for (int j = 0; j < 4; j++)
                    MMA16816(acc[m][j], a0, a1, a2, a3, bf[j][0], bf[j][1]);
            }
        }
        #pragma unroll
        for (int m = 0; m < 4; m++) {
            int r1 = m * 16 + qr, r2 = r1 + 8;
            #pragma unroll
            for (int j = 0; j < 4; j++) {
                float bb0 = s[OFN_B2 + n0 + 8 * j + 2 * qc];
                float bb1 = s[OFN_B2 + n0 + 8 * j + 2 * qc + 1];
                uint32_t u = n0 / 2 + 4 * j + qc;
                s32[YNU + r1 * 132 + u] =
                    cvt_f16x2(lrelu(acc[m][j][1] + bb1), lrelu(acc[m][j][0] + bb0));
                s32[YNU + r2 * 132 + u] =
                    cvt_f16x2(lrelu(acc[m][j][3] + bb1), lrelu(acc[m][j][2] + bb0));
            }
        }
    }
    __syncthreads();

    // ---- Phase 3: out[64][3] = h2 @ W3 + b3 (half2-paired fp32) ----
    if (tid < 192) {
        int r = tid / 3, o = tid - r * 3;
        const __half2* hr = (const __half2*)(sh + BYN / 2 + r * 264);
        float a = s[OFN_B3 + o];
        #pragma unroll 8
        for (int k2 = 0; k2 < 128; k2++) {
            float2 h = __half22float2(hr[k2]);
            a += h.x * s[OFN_W3 + 6 * k2 + o] + h.y * s[OFN_W3 + 6 * k2 + 3 + o];
        }
        out[(row0 + r) * 3 + o] = a;
    }
}

extern "C" void kernel_launch(void* const* d_in, const int* in_sizes, int n_in,
                              void* d_out, int out_size)
{
    const float* x    = (const float*)d_in[0];
    const float* few1 = (const float*)d_in[1];
    const float* feb1 = (const float*)d_in[2];
    const float* few2 = (const float*)d_in[3];
    const float* feb2 = (const float*)d_in[4];
    const float* few3 = (const float*)d_in[5];
    const float* feb3 = (const float*)d_in[6];
    const float* fnw1 = (const float*)d_in[7];
    const float* fnb1 = (const float*)d_in[8];
    const float* fnw2 = (const float*)d_in[9];
    const float* fnb2 = (const float*)d_in[10];
    const float* fnw3 = (const float*)d_in[11];
    const float* fnb3 = (const float*)d_in[12];
    float* out = (float*)d_out;

    cudaFuncSetAttribute(edge_kernel, cudaFuncAttributeMaxDynamicSharedMemorySize, SMEM1_BYTES);
    cudaFuncSetAttribute(node_kernel, cudaFuncAttributeMaxDynamicSharedMemorySize, SMEM2_BYTES);

    prep_kernel<<<132, 256>>>(fnw1, fnw2);
    edge_kernel<<<148, 256, SMEM1_BYTES>>>(x, few1, feb1, few2, feb2, few3, feb3);
    node_kernel<<<150, 256, SMEM2_BYTES>>>(x, fnb1, fnb2, fnw3, fnb3, out);
}

// round 10
// speedup vs baseline: 7.0886x; 1.0524x over previous
#include <cuda_runtime.h>
#include <cuda_fp16.h>
#include <cstdint>

#define ALPHA 0.2f

// Aggregated edge features scratch: [128*75, 192] = 7.37 MB (static, allowed)
static __device__ float g_agg[9600 * 192];
// Pre-converted fp16 node weights, already in node-SMEM layout (u32 = f16x2, stride 132)
static __device__ uint4 g_w1h[208 * 132 / 4];   // 195x256 valid, zero-padded
static __device__ uint4 g_w2h[256 * 132 / 4];

__device__ __forceinline__ float lrelu(float v) { return v > 0.0f ? v : ALPHA * v; }

// ---- packed fp32 helpers ----
#define FFMA2(acc, a, b) \
    asm("fma.rn.f32x2 %0, %1, %2, %0;" : "+l"(acc) : "l"(a), "l"(b))
__device__ __forceinline__ float2 unpack2(unsigned long long v) {
    float2 r;
    asm("mov.b64 {%0, %1}, %2;" : "=f"(r.x), "=f"(r.y) : "l"(v));
    return r;
}
__device__ __forceinline__ unsigned long long pack2(float lo, float hi) {
    unsigned long long r;
    asm("mov.b64 %0, {%1, %2};" : "=l"(r) : "f"(lo), "f"(hi));
    return r;
}
// pack two f32 -> f16x2 word: halves[0] = lo, halves[1] = hi
__device__ __forceinline__ uint32_t cvt_f16x2(float hi, float lo) {
    uint32_t d;
    asm("cvt.rn.f16x2.f32 %0, %1, %2;" : "=r"(d) : "f"(hi), "f"(lo));
    return d;
}
__device__ __forceinline__ uint32_t smem_u32(const void* p) {
    uint32_t a;
    asm("{ .reg .u64 t; cvta.to.shared.u64 t, %1; cvt.u32.u64 %0, t; }"
        : "=r"(a) : "l"(p));
    return a;
}

// ---- warp-level tensor core (sm_80+ path; valid on plain sm_103) ----
#define LDSM_X4(a0, a1, a2, a3, addr) \
    asm volatile("ldmatrix.sync.aligned.m8n8.x4.shared.b16 {%0,%1,%2,%3}, [%4];" \
                 : "=r"(a0), "=r"(a1), "=r"(a2), "=r"(a3) : "r"(addr))
#define LDSM_X2T(b0, b1, addr) \
    asm volatile("ldmatrix.sync.aligned.m8n8.x2.trans.shared.b16 {%0,%1}, [%2];" \
                 : "=r"(b0), "=r"(b1) : "r"(addr))
#define MMA16816(c, a0, a1, a2, a3, b0, b1) \
    asm volatile("mma.sync.aligned.m16n8k16.row.col.f32.f16.f16.f32 " \
                 "{%0,%1,%2,%3}, {%4,%5,%6,%7}, {%8,%9}, {%0,%1,%2,%3};" \
                 : "+f"((c)[0]), "+f"((c)[1]), "+f"((c)[2]), "+f"((c)[3]) \
                 : "r"(a0), "r"(a1), "r"(a2), "r"(a3), "r"(b0), "r"(b1))

// ================= PREP KERNEL: fn weights -> fp16 layout =================
__global__ void __launch_bounds__(256)
prep_kernel(const float* __restrict__ w1, const float* __restrict__ w2)
{
    int i = blockIdx.x * 256 + threadIdx.x;
    if (i < 208 * 132) {
        int k = i / 132, u = i - k * 132;
        uint32_t v = 0u;
        if (k < 195 && u < 128)
            v = cvt_f16x2(w1[(size_t)k * 256 + 2 * u + 1], w1[(size_t)k * 256 + 2 * u]);
        ((uint32_t*)g_w1h)[i] = v;
    }
    if (i < 256 * 132) {
        int k = i / 132, u = i - k * 132;
        uint32_t v = 0u;
        if (u < 128)
            v = cvt_f16x2(w2[(size_t)k * 256 + 2 * u + 1], w2[(size_t)k * 256 + 2 * u]);
        ((uint32_t*)g_w2h)[i] = v;
    }
}

// ================= EDGE KERNEL =================
#define BW2 0        // W2 fp16 [96 k][168 n-stride]  (160 used)  = 32256 B
#define BW3 32256    // W3 fp16 [160 k][200 n-stride] (192 used)  = 64000 B
#define BH1 96256    // h1 fp16 [80 m][104 k-stride]  (96 used)   = 16640 B
#define BH2 112896   // h2 fp16 [80 m][168 k-stride]  (160 used)  = 26880 B
#define OF_W1 34944  // 672
#define OF_B2 35616  // 160
#define OF_B3 35776  // 192
#define OF_UI 35968  // 96
#define OF_XJ 36064  // 228
#define OF_D  36292  // 76
#define SMEM1_FL 36368
#define SMEM1_BYTES (SMEM1_FL * 4)
#define H1B32 (BH1 / 4)
#define H2B32 (BH2 / 4)

__global__ void __launch_bounds__(256, 1)
edge_kernel(const float* __restrict__ x,
            const float* __restrict__ w1, const float* __restrict__ b1,
            const float* __restrict__ w2, const float* __restrict__ b2,
            const float* __restrict__ w3, const float* __restrict__ b3)
{
    extern __shared__ float s[];
    uint32_t* s32 = (uint32_t*)s;
    __half* sh = (__half*)s;
    const int tid = threadIdx.x;
    const int wid = tid >> 5;
    const int lane = tid & 31;
    const uint32_t sbase = smem_u32(s);

    for (int i = tid; i < 672; i += 256) s[OF_W1 + i] = w1[i];
    for (int i = tid; i < 160; i += 256) s[OF_B2 + i] = b2[i];
    for (int i = tid; i < 192; i += 256) s[OF_B3 + i] = b3[i];
    for (int idx = tid; idx < 96 * 160; idx += 256) {
        int k = idx / 160, n = idx - k * 160;
        sh[k * 168 + n] = __float2half(w2[idx]);
    }
    for (int idx = tid; idx < 160 * 192; idx += 256) {
        int k = idx / 192, n = idx - k * 192;
        sh[BW3 / 2 + k * 200 + n] = __float2half(w3[idx]);
    }
    for (int idx = tid; idx < 5 * 52; idx += 256)
        s32[H1B32 + (75 + idx / 52) * 52 + (idx % 52)] = 0u;
    __syncthreads();

    const int nt1 = (wid < 4) ? 3 : 2;
    int n1[3], n2[3];
    #pragma unroll
    for (int j = 0; j < 3; j++) { n1[j] = 8 * wid + 64 * j; n2[j] = 8 * wid + 64 * j; }
    const int lA = lane & 15, gA = lane >> 4;
    const int lB = lane & 15;
    const int qr = lane >> 2, qc = lane & 3;
    const uint32_t a1base = sbase + BH1 + (uint32_t)(lA * 104 + gA * 8) * 2;
    const uint32_t a2base = sbase + BH2 + (uint32_t)(lA * 168 + gA * 8) * 2;
    const uint32_t b2base = sbase + BW2 + (uint32_t)(lB * 168) * 2;
    const uint32_t b3base = sbase + BW3 + (uint32_t)(lB * 200) * 2;
    float e1b0[3], e1b1[3], e2b0[3], e2b1[3];
    #pragma unroll
    for (int j = 0; j < 3; j++) {
        if (j < nt1) {
            e1b0[j] = s[OF_B2 + n1[j] + 2 * qc];
            e1b1[j] = s[OF_B2 + n1[j] + 2 * qc + 1];
        } else { e1b0[j] = 0.f; e1b1[j] = 0.f; }
        e2b0[j] = s[OF_B3 + n2[j] + 2 * qc];
        e2b1[j] = s[OF_B3 + n2[j] + 2 * qc + 1];
    }

    // ---- Hoist ALL loop-invariant B fragments into registers ----
    uint32_t bf2[6][3][2];     // W2 frags: 36 regs (j=2 unused on warps 4-7)
    uint32_t bf3[10][3][2];    // W3 frags: 60 regs
    #pragma unroll
    for (int k = 0; k < 6; k++)
        #pragma unroll
        for (int j = 0; j < 3; j++) {
            if (j < nt1) { LDSM_X2T(bf2[k][j][0], bf2[k][j][1], b2base + k * 5376 + n1[j] * 2); }
            else { bf2[k][j][0] = 0u; bf2[k][j][1] = 0u; }
        }
    #pragma unroll
    for (int k = 0; k < 10; k++)
        #pragma unroll
        for (int j = 0; j < 3; j++)
            LDSM_X2T(bf3[k][j][0], bf3[k][j][1], b3base + k * 6400 + n2[j] * 2);

    for (int bi = blockIdx.x; bi < 9600; bi += gridDim.x) {
        const int b = bi / 75, i = bi % 75;
        const float* xb = x + b * 75 * 3;
        const float xi0 = xb[i * 3 + 0], xi1 = xb[i * 3 + 1], xi2 = xb[i * 3 + 2];

        if (tid < 75) {
            float a0 = xb[tid * 3 + 0], a1 = xb[tid * 3 + 1], a2 = xb[tid * 3 + 2];
            s[OF_XJ + 3 * tid + 0] = a0;
            s[OF_XJ + 3 * tid + 1] = a1;
            s[OF_XJ + 3 * tid + 2] = a2;
            float d0 = (a0 - xi0) + 1e-12f;
            float d1 = (a1 - xi1) + 1e-12f;
            float d2 = (a2 - xi2) + 1e-12f;
            s[OF_D + tid] = sqrtf(d0 * d0 + d1 * d1 + d2 * d2);
        }
        if (tid >= 160) {
            int c = tid - 160;
            s[OF_UI + c] = b1[c] + xi0 * s[OF_W1 + c]
                                 + xi1 * s[OF_W1 + 96 + c]
                                 + xi2 * s[OF_W1 + 192 + c];
        }
        __syncthreads();

        for (int idx = tid; idx < 75 * 48; idx += 256) {
            int r = idx / 48, w = idx - r * 48;
            float xj0 = s[OF_XJ + 3 * r + 0];
            float xj1 = s[OF_XJ + 3 * r + 1];
            float xj2 = s[OF_XJ + 3 * r + 2];
            float dj  = s[OF_D + r];
            unsigned long long v = *(const unsigned long long*)(s + OF_UI + 2 * w);
            FFMA2(v, pack2(xj0, xj0), *(const unsigned long long*)(s + OF_W1 + 288 + 2 * w));
            FFMA2(v, pack2(xj1, xj1), *(const unsigned long long*)(s + OF_W1 + 384 + 2 * w));
            FFMA2(v, pack2(xj2, xj2), *(const unsigned long long*)(s + OF_W1 + 480 + 2 * w));
            FFMA2(v, pack2(dj, dj),   *(const unsigned long long*)(s + OF_W1 + 576 + 2 * w));
            float2 vf = unpack2(v);
            s32[H1B32 + r * 52 + w] = cvt_f16x2(lrelu(vf.y), lrelu(vf.x));
        }
        __syncthreads();

        // ---- MMA1: D1[80][160] = h1 @ W2 ; epi -> h2 fp16 ----
        {
            float acc[5][3][4];
            #pragma unroll
            for (int m = 0; m < 5; m++)
                #pragma unroll
                for (int j = 0; j < 3; j++)
                    { acc[m][j][0]=0.f; acc[m][j][1]=0.f; acc[m][j][2]=0.f; acc[m][j][3]=0.f; }
            #pragma unroll
            for (int k = 0; k < 6; k++) {
                #pragma unroll
                for (int m = 0; m < 5; m++) {
                    uint32_t a0, a1, a2, a3;
                    LDSM_X4(a0, a1, a2, a3, a1base + m * 3328 + k * 32);
                    #pragma unroll
                    for (int j = 0; j < 3; j++)
                        if (j < nt1) MMA16816(acc[m][j], a0, a1, a2, a3, bf2[k][j][0], bf2[k][j][1]);
                }
            }
            #pragma unroll
            for (int m = 0; m < 5; m++) {
                int r1 = m * 16 + qr, r2 = r1 + 8;
                #pragma unroll
                for (int j = 0; j < 3; j++)
                    if (j < nt1) {
                        uint32_t u = n1[j] / 2 + qc;
                        s32[H2B32 + r1 * 84 + u] =
                            cvt_f16x2(lrelu(acc[m][j][1] + e1b1[j]),
                                      lrelu(acc[m][j][0] + e1b0[j]));
                        s32[H2B32 + r2 * 84 + u] =
                            cvt_f16x2(lrelu(acc[m][j][3] + e1b1[j]),
                                      lrelu(acc[m][j][2] + e1b0[j]));
                    }
            }
        }
        __syncthreads();

        // ---- MMA2: D2[80][192] = h2 @ W3 (B frags in registers) ----
        {
            float acc[5][3][4];
            #pragma unroll
            for (int m = 0; m < 5; m++)
                #pragma unroll
                for (int j = 0; j < 3; j++)
                    { acc[m][j][0]=0.f; acc[m][j][1]=0.f; acc[m][j][2]=0.f; acc[m][j][3]=0.f; }
            #pragma unroll
            for (int k = 0; k < 10; k++) {
                #pragma unroll
                for (int m = 0; m < 5; m++) {
                    uint32_t a0, a1, a2, a3;
                    LDSM_X4(a0, a1, a2, a3, a2base + m * 5376 + k * 32);
                    #pragma unroll
                    for (int j = 0; j < 3; j++)
                        MMA16816(acc[m][j], a0, a1, a2, a3, bf3[k][j][0], bf3[k][j][1]);
                }
            }
            float cs0[3] = {0.f, 0.f, 0.f}, cs1[3] = {0.f, 0.f, 0.f};
            #pragma unroll
            for (int m = 0; m < 5; m++) {
                bool ok2 = (m * 16 + 8 + qr) < 75;
                #pragma unroll
                for (int j = 0; j < 3; j++) {
                    cs0[j] += lrelu(acc[m][j][0] + e2b0[j]);
                    cs1[j] += lrelu(acc[m][j][1] + e2b1[j]);
                    if (ok2) {
                        cs0[j] += lrelu(acc[m][j][2] + e2b0[j]);
                        cs1[j] += lrelu(acc[m][j][3] + e2b1[j]);
                    }
                }
            }
            #pragma unroll
            for (int j = 0; j < 3; j++) {
                #pragma unroll
                for (int d = 4; d < 32; d <<= 1) {
                    cs0[j] += __shfl_xor_sync(0xFFFFFFFFu, cs0[j], d);
                    cs1[j] += __shfl_xor_sync(0xFFFFFFFFu, cs1[j], d);
                }
            }
            if (lane < 4) {
                float* gp = g_agg + bi * 192;
                #pragma unroll
                for (int j = 0; j < 3; j++) {
                    gp[n2[j] + 2 * lane]     = cs0[j];
                    gp[n2[j] + 2 * lane + 1] = cs1[j];
                }
            }
        }
        __syncthreads();
    }
}

// ================= NODE KERNEL — HMMA =================
#define BWN   0
#define BH1N  135168
#define BYN   168960
#define OFN_B1 50688
#define OFN_B2 50944
#define OFN_W3 51200
#define OFN_B3 51968
#define SMEM2_FL 51972
#define SMEM2_BYTES (SMEM2_FL * 4)
#define H1NU (BH1N / 4)
#define YNU  (BYN / 4)

__global__ void __launch_bounds__(256, 1)
node_kernel(const float* __restrict__ x,
            const float* __restrict__ b1,
            const float* __restrict__ b2,
            const float* __restrict__ w3, const float* __restrict__ b3,
            float* __restrict__ out)
{
    extern __shared__ float s[];
    uint32_t* s32 = (uint32_t*)s;
    __half* sh = (__half*)s;
    const int tid = threadIdx.x;
    const int wid = tid >> 5;
    const int lane = tid & 31;
    const uint32_t sbase = smem_u32(s);
    const int row0 = blockIdx.x * 64;

    const int lA = lane & 15, gA = lane >> 4;
    const int lB = lane & 15;
    const int qr = lane >> 2, qc = lane & 3;
    const int n0 = 32 * wid;
    const uint32_t aYbase  = sbase + BYN  + (uint32_t)(lA * 216 + gA * 8) * 2;
    const uint32_t aH1base = sbase + BH1N + (uint32_t)(lA * 264 + gA * 8) * 2;
    const uint32_t bWbase  = sbase + BWN  + (uint32_t)(lB * 264) * 2;

    // ---- Stage 0: biases/w3 + y tile + W1 fp16 (pure uint4 copy) ----
    for (int i = tid; i < 256; i += 256) s[OFN_B1 + i] = b1[i];
    for (int i = tid; i < 256; i += 256) s[OFN_B2 + i] = b2[i];
    for (int i = tid; i < 768; i += 256) s[OFN_W3 + i] = w3[i];
    if (tid < 3) s[OFN_B3 + tid] = b3[tid];

    for (int idx = tid; idx < 64 * 108; idx += 256) {
        int r = idx / 108, u = idx - r * 108;
        int gr = row0 + r;
        uint32_t v;
        if (u < 96) {
            const float* gp = g_agg + (size_t)gr * 192 + 2 * u;
            v = cvt_f16x2(gp[1], gp[0]);
        } else if (u == 96) {
            v = cvt_f16x2(x[gr * 3 + 1], x[gr * 3 + 0]);
        } else if (u == 97) {
            v = cvt_f16x2(0.f, x[gr * 3 + 2]);
        } else v = 0u;
        s32[YNU + r * 108 + u] = v;
    }
    {
        uint4* d = (uint4*)s32;
        for (int i = tid; i < 208 * 132 / 4; i += 256) d[i] = g_w1h[i];
    }
    __syncthreads();

    // ---- Phase 1: h1[64][256] = lrelu(y @ W1 + b1), K = 208 ----
    {
        float acc[4][4][4];
        #pragma unroll
        for (int m = 0; m < 4; m++)
            #pragma unroll
            for (int j = 0; j < 4; j++)
                { acc[m][j][0]=0.f; acc[m][j][1]=0.f; acc[m][j][2]=0.f; acc[m][j][3]=0.f; }
        #pragma unroll
        for (int kc = 0; kc < 13; kc++) {
            uint32_t bf[4][2];
            #pragma unroll
            for (int j = 0; j < 4; j++)
                LDSM_X2T(bf[j][0], bf[j][1], bWbase + kc * 8448 + (n0 + 8 * j) * 2);
            #pragma unroll
            for (int m = 0; m < 4; m++) {
                uint32_t a0, a1, a2, a3;
                LDSM_X4(a0, a1, a2, a3, aYbase + m * 6912 + kc * 32);
                #pragma unroll
                for (int j = 0; j < 4; j++)
                    MMA16816(acc[m][j], a0, a1, a2, a3, bf[j][0], bf[j][1]);
            }
        }
        #pragma unroll
        for (int m = 0; m < 4; m++) {
            int r1 = m * 16 + qr, r2 = r1 + 8;
            #pragma unroll
            for (int j = 0; j < 4; j++) {
                float bb0 = s[OFN_B1 + n0 + 8 * j + 2 * qc];
                float bb1 = s[OFN_B1 + n0 + 8 * j + 2 * qc + 1];
                uint32_t u = n0 / 2 + 4 * j + qc;
                s32[H1NU + r1 * 132 + u] =
                    cvt_f16x2(lrelu(acc[m][j][1] + bb1), lrelu(acc[m][j][0] + bb0));
                s32[H1NU + r2 * 132 + u] =
                    cvt_f16x2(lrelu(acc[m][j][3] + bb1), lrelu(acc[m][j][2] + bb0));
            }
        }
    }
    __syncthreads();

    // ---- Stage: W2 fp16 (pure uint4 copy) ----
    {
        uint4* d = (uint4*)s32;
        for (int i = tid; i < 256 * 132 / 4; i += 256) d[i] = g_w2h[i];
    }
    __syncthreads();

    // ---- Phase 2: h2[64][256] = lrelu(h1 @ W2 + b2), K = 256 ----
    {
        float acc[4][4][4];
        #pragma unroll
        for (int m = 0; m < 4; m++)
            #pragma unroll
            for (int j = 0; j < 4; j++)
                { acc[m][j][0]=0.f; acc[m][j][1]=0.f; acc[m][j][2]=0.f; acc[m][j][3]=0.f; }
        #pragma unroll
        for (int kc = 0; kc < 16; kc++) {
            uint32_t bf[4][2];
            #pragma unroll
            for (int j = 0; j < 4; j++)
                LDSM_X2T(bf[j][0], bf[j][1], bWbase + kc * 8448 + (n0 + 8 * j) * 2);
            #pragma unroll
            for (int m = 0; m < 4; m++) {
                uint32_t a0, a1, a2, a3;
                LDSM_X4(a0, a1, a2, a3, aH1base + m * 8448 + kc * 32);
                #pragma unroll
                for (int j = 0; j < 4; j++)
                    MMA16816(acc[m][j], a0, a1, a2, a3, bf[j][0], bf[j][1]);
            }
        }
        #pragma unroll
        for (int m = 0; m < 4; m++) {
            int r1 = m * 16 + qr, r2 = r1 + 8;
            #pragma unroll
            for (int j = 0; j < 4; j++) {
                float bb0 = s[OFN_B2 + n0 + 8 * j + 2 * qc];
                float bb1 = s[OFN_B2 + n0 + 8 * j + 2 * qc + 1];
                uint32_t u = n0 / 2 + 4 * j + qc;
                s32[YNU + r1 * 132 + u] =
                    cvt_f16x2(lrelu(acc[m][j][1] + bb1), lrelu(acc[m][j][0] + bb0));
                s32[YNU + r2 * 132 + u] =
                    cvt_f16x2(lrelu(acc[m][j][3] + bb1), lrelu(acc[m][j][2] + bb0));
            }
        }
    }
    __syncthreads();

    // ---- Phase 3: out[64][3] = h2 @ W3 + b3 (half2-paired fp32) ----
    if (tid < 192) {
        int r = tid / 3, o = tid - r * 3;
        const __half2* hr = (const __half2*)(sh + BYN / 2 + r * 264);
        float a = s[OFN_B3 + o];
        #pragma unroll 8
        for (int k2 = 0; k2 < 128; k2++) {
            float2 h = __half22float2(hr[k2]);
            a += h.x * s[OFN_W3 + 6 * k2 + o] + h.y * s[OFN_W3 + 6 * k2 + 3 + o];
        }
        out[(row0 + r) * 3 + o] = a;
    }
}

extern "C" void kernel_launch(void* const* d_in, const int* in_sizes, int n_in,
                              void* d_out, int out_size)
{
    const float* x    = (const float*)d_in[0];
    const float* few1 = (const float*)d_in[1];
    const float* feb1 = (const float*)d_in[2];
    const float* few2 = (const float*)d_in[3];
    const float* feb2 = (const float*)d_in[4];
    const float* few3 = (const float*)d_in[5];
    const float* feb3 = (const float*)d_in[6];
    const float* fnw1 = (const float*)d_in[7];
    const float* fnb1 = (const float*)d_in[8];
    const float* fnw2 = (const float*)d_in[9];
    const float* fnb2 = (const float*)d_in[10];
    const float* fnw3 = (const float*)d_in[11];
    const float* fnb3 = (const float*)d_in[12];
    float* out = (float*)d_out;

    cudaFuncSetAttribute(edge_kernel, cudaFuncAttributeMaxDynamicSharedMemorySize, SMEM1_BYTES);
    cudaFuncSetAttribute(node_kernel, cudaFuncAttributeMaxDynamicSharedMemorySize, SMEM2_BYTES);

    prep_kernel<<<132, 256>>>(fnw1, fnw2);
    edge_kernel<<<148, 256, SMEM1_BYTES>>>(x, few1, feb1, few2, feb2, few3, feb3);
    node_kernel<<<150, 256, SMEM2_BYTES>>>(x, fnb1, fnb2, fnw3, fnb3, out);
}